// round 3
// baseline (speedup 1.0000x reference)
#include <cuda_runtime.h>
#include <cstdint>

// Problem constants (fixed shapes)
#define Nn 50000
#define Ee 640000
#define Dd 128

// ---------------- device scratch (static; no allocations allowed) --------
__device__ float g_U[Nn * Dd];                    // x @ Wu^T + bu
__device__ float g_B[Nn * Dd];                    // x @ WB^T + bB
__device__ float g_CV[Nn * 2 * Dd];               // per node: [Cx(128) | Vx(128)]
__device__ float g_edge_in[(size_t)Ee * Dd];      // pre-BN edge activations
__device__ float g_agg[Nn * Dd];                  // segment-sum of messages
__device__ float g_stats[1024];                   // [0:128) e_sum [128:256) e_sumsq
                                                  // [256:384) n_sum [384:512) n_sumsq
                                                  // [512..) e_mean,e_rstd,n_mean,n_rstd
__device__ int g_is64;                            // edge_index dtype flag

// ---------------- helpers ------------------------------------------------
__device__ __forceinline__ unsigned long long ffma2(unsigned long long a,
                                                    unsigned long long b,
                                                    unsigned long long c) {
    unsigned long long d;
    asm("fma.rn.f32x2 %0, %1, %2, %3;" : "=l"(d) : "l"(a), "l"(b), "l"(c));
    return d;
}

// Detect int64 vs int32 edge_index: sample 2048 high words; all-zero => int64.
__global__ void detect_kernel(const unsigned* __restrict__ w) {
    __shared__ int sflag;
    if (threadIdx.x == 0) sflag = 0;
    __syncthreads();
    unsigned v = 0;
    for (int i = threadIdx.x; i < 2048; i += blockDim.x) v |= w[2 * i + 1];
    if (v) atomicOr(&sflag, 1);
    __syncthreads();
    if (threadIdx.x == 0) g_is64 = sflag ? 0 : 1;
}

__global__ void zero_kernel() {
    int i = blockIdx.x * blockDim.x + threadIdx.x;
    const int total = Nn * Dd;
    for (int k = i; k < total; k += gridDim.x * blockDim.x) g_agg[k] = 0.f;
    if (i < 1024) g_stats[i] = 0.f;
}

// ---------------- K1: node GEMMs (4 matrices via blockIdx.y) -------------
// Block: 128 threads (one per output feature), 32 nodes per block.
// Weight staged in smem with stride-130 rows; inner loop is packed f32x2 FMA.
__global__ void node_gemm_kernel(const float* __restrict__ x,
                                 const float* __restrict__ Wu, const float* __restrict__ bu,
                                 const float* __restrict__ Wv, const float* __restrict__ bv,
                                 const float* __restrict__ WB, const float* __restrict__ bB,
                                 const float* __restrict__ WC, const float* __restrict__ bC) {
    extern __shared__ float sm[];
    float* ws = sm;                 // 128*130 floats
    float* xs = sm + 128 * 130;     // 32*128 floats
    const int tid = threadIdx.x;
    const int which = blockIdx.y;

    const float* W;
    const float* bias;
    if (which == 0)      { W = Wu; bias = bu; }
    else if (which == 1) { W = Wv; bias = bv; }
    else if (which == 2) { W = WB; bias = bB; }
    else                 { W = WC; bias = bC; }

    const float4* W4 = (const float4*)W;
    for (int i = tid; i < 4096; i += 128) {
        float4 v = W4[i];
        int f = i >> 5;
        int k = (i & 31) << 2;
        float* dst = ws + f * 130 + k;
        dst[0] = v.x; dst[1] = v.y; dst[2] = v.z; dst[3] = v.w;
    }
    const int n0 = blockIdx.x * 32;
    for (int i = tid; i < 32 * 32; i += 128) {
        int n = i >> 5;
        int node = n0 + n;
        float4 v = (node < Nn) ? ((const float4*)x)[(size_t)node * 32 + (i & 31)]
                               : make_float4(0.f, 0.f, 0.f, 0.f);
        *(float4*)(xs + n * 128 + ((i & 31) << 2)) = v;
    }
    __syncthreads();

    const int f = tid;
    unsigned long long acc[32];
#pragma unroll
    for (int n = 0; n < 32; n++) acc[n] = 0ULL;
    const unsigned long long* wrow = (const unsigned long long*)(ws + f * 130);
#pragma unroll 2
    for (int j = 0; j < 64; j++) {
        unsigned long long w2 = wrow[j];
#pragma unroll
        for (int n = 0; n < 32; n++) {
            unsigned long long x2 = *(const unsigned long long*)(xs + n * 128 + 2 * j);
            acc[n] = ffma2(x2, w2, acc[n]);
        }
    }
    float bf = bias[f];
    float* base;
    int rstride, off;
    if (which == 0)      { base = g_U;  rstride = 128; off = 0;   }
    else if (which == 1) { base = g_CV; rstride = 256; off = 128; }
    else if (which == 2) { base = g_B;  rstride = 128; off = 0;   }
    else                 { base = g_CV; rstride = 256; off = 0;   }
#pragma unroll
    for (int n = 0; n < 32; n++) {
        int node = n0 + n;
        if (node < Nn) {
            float lo = __uint_as_float((unsigned)acc[n]);
            float hi = __uint_as_float((unsigned)(acc[n] >> 32));
            base[(size_t)node * rstride + off + f] = lo + hi + bf;
        }
    }
}

// ---------------- K2: edge GEMM + gathers + BN stats (pass 1) ------------
__global__ void edge_gemm_kernel(const float* __restrict__ ea, const void* __restrict__ eidx,
                                 const float* __restrict__ WA, const float* __restrict__ bA) {
    extern __shared__ float sm[];
    float* ws = sm;                         // 128*130
    float* es = sm + 128 * 130;             // 32*128
    int* rows = (int*)(es + 32 * 128);
    int* cols = rows + 32;
    const int tid = threadIdx.x;

    const float4* W4 = (const float4*)WA;
    for (int i = tid; i < 4096; i += 128) {
        float4 v = W4[i];
        int f = i >> 5;
        int k = (i & 31) << 2;
        float* dst = ws + f * 130 + k;
        dst[0] = v.x; dst[1] = v.y; dst[2] = v.z; dst[3] = v.w;
    }
    const int e0 = blockIdx.x * 32;
    const float4* src = (const float4*)(ea + (size_t)e0 * 128);
    float4* dst4 = (float4*)es;
    for (int i = tid; i < 1024; i += 128) dst4[i] = src[i];
    if (tid < 32) {
        long idx = e0 + tid;
        rows[tid] = g_is64 ? (int)((const long long*)eidx)[idx] : ((const int*)eidx)[idx];
    } else if (tid < 64) {
        long idx = (long)Ee + e0 + (tid - 32);
        cols[tid - 32] = g_is64 ? (int)((const long long*)eidx)[idx] : ((const int*)eidx)[idx];
    }
    __syncthreads();

    const int f = tid;
    unsigned long long acc[32];
#pragma unroll
    for (int n = 0; n < 32; n++) acc[n] = 0ULL;
    const unsigned long long* wrow = (const unsigned long long*)(ws + f * 130);
#pragma unroll 2
    for (int j = 0; j < 64; j++) {
        unsigned long long w2 = wrow[j];
#pragma unroll
        for (int n = 0; n < 32; n++) {
            unsigned long long x2 = *(const unsigned long long*)(es + n * 128 + 2 * j);
            acc[n] = ffma2(x2, w2, acc[n]);
        }
    }
    float bf = bA[f];
    float s1 = 0.f, s2 = 0.f;
#pragma unroll 4
    for (int n = 0; n < 32; n++) {
        float lo = __uint_as_float((unsigned)acc[n]);
        float hi = __uint_as_float((unsigned)(acc[n] >> 32));
        float v = lo + hi + bf
                + g_B[(size_t)rows[n] * 128 + f]
                + g_CV[(size_t)cols[n] * 256 + f];
        g_edge_in[(size_t)(e0 + n) * 128 + f] = v;
        s1 += v;
        s2 += v * v;
    }
    atomicAdd(&g_stats[f], s1);
    atomicAdd(&g_stats[128 + f], s2);
}

// ---------------- finalize BN stats (which: 0=edge, 1=node) --------------
__global__ void finalize_kernel(int which, float inv) {
    int f = threadIdx.x;
    float s1 = g_stats[which * 256 + f];
    float s2 = g_stats[which * 256 + 128 + f];
    float mean = s1 * inv;
    float var = fmaxf(s2 * inv - mean * mean, 0.f);
    g_stats[512 + which * 256 + f] = mean;
    g_stats[512 + which * 256 + 128 + f] = rsqrtf(var + 1e-5f);
}

// ---------------- K4: edge pass 2 (BN+relu+residual, messages, segsum) ---
__global__ void edge_pass2_kernel(const float* __restrict__ ea, const void* __restrict__ eidx,
                                  const float* __restrict__ gam, const float* __restrict__ bet,
                                  float* __restrict__ out_e) {
    int e = blockIdx.x * 8 + (threadIdx.x >> 5);
    if (e >= Ee) return;
    int c = (threadIdx.x & 31) * 4;
    int row, col;
    if (g_is64) {
        const long long* p = (const long long*)eidx;
        row = (int)p[e];
        col = (int)p[(size_t)Ee + e];
    } else {
        const int* p = (const int*)eidx;
        row = p[e];
        col = p[Ee + e];
    }
    size_t base = (size_t)e * 128 + c;
    float4 ein = *(const float4*)(g_edge_in + base);
    float4 mu = *(const float4*)(g_stats + 512 + c);
    float4 rs = *(const float4*)(g_stats + 640 + c);
    float4 gm = __ldg((const float4*)(gam + c));
    float4 bt = __ldg((const float4*)(bet + c));
    float4 a4 = __ldg((const float4*)(ea + base));
    float4 eo;
    eo.x = a4.x + fmaxf(gm.x * (ein.x - mu.x) * rs.x + bt.x, 0.f);
    eo.y = a4.y + fmaxf(gm.y * (ein.y - mu.y) * rs.y + bt.y, 0.f);
    eo.z = a4.z + fmaxf(gm.z * (ein.z - mu.z) * rs.z + bt.z, 0.f);
    eo.w = a4.w + fmaxf(gm.w * (ein.w - mu.w) * rs.w + bt.w, 0.f);
    *(float4*)(out_e + base) = eo;

    float4 v4 = *(const float4*)(g_CV + (size_t)col * 256 + 128 + c);
    float mx = v4.x / (1.f + __expf(-eo.x));
    float my = v4.y / (1.f + __expf(-eo.y));
    float mz = v4.z / (1.f + __expf(-eo.z));
    float mw = v4.w / (1.f + __expf(-eo.w));
    float* dst = g_agg + (size_t)row * 128 + c;
    asm volatile("red.global.add.v4.f32 [%0], {%1, %2, %3, %4};"
                 :: "l"(dst), "f"(mx), "f"(my), "f"(mz), "f"(mw) : "memory");
}

// ---------------- K5: node BN stats --------------------------------------
__global__ void node_stats_kernel() {
    int f = threadIdx.x;
    int n0 = blockIdx.x * 64;
    float s1 = 0.f, s2 = 0.f;
    for (int r = 0; r < 64; r++) {
        int n = n0 + r;
        if (n < Nn) {
            float v = g_U[(size_t)n * 128 + f] + g_agg[(size_t)n * 128 + f];
            s1 += v;
            s2 += v * v;
        }
    }
    atomicAdd(&g_stats[256 + f], s1);
    atomicAdd(&g_stats[384 + f], s2);
}

// ---------------- K6: node output ----------------------------------------
__global__ void node_out_kernel(const float* __restrict__ x, const float* __restrict__ gam,
                                const float* __restrict__ bet, float* __restrict__ out_x) {
    int i = blockIdx.x * blockDim.x + threadIdx.x;
    if (i >= Nn * 32) return;
    int c = (i & 31) * 4;
    size_t base = (size_t)i * 4;
    float4 u = *(const float4*)(g_U + base);
    float4 a = *(const float4*)(g_agg + base);
    float4 mu = *(const float4*)(g_stats + 768 + c);
    float4 rs = *(const float4*)(g_stats + 896 + c);
    float4 gm = __ldg((const float4*)(gam + c));
    float4 bt = __ldg((const float4*)(bet + c));
    float4 xv = __ldg((const float4*)(x + base));
    float4 o;
    o.x = xv.x + fmaxf(gm.x * ((u.x + a.x) - mu.x) * rs.x + bt.x, 0.f);
    o.y = xv.y + fmaxf(gm.y * ((u.y + a.y) - mu.y) * rs.y + bt.y, 0.f);
    o.z = xv.z + fmaxf(gm.z * ((u.z + a.z) - mu.z) * rs.z + bt.z, 0.f);
    o.w = xv.w + fmaxf(gm.w * ((u.w + a.w) - mu.w) * rs.w + bt.w, 0.f);
    *(float4*)(out_x + base) = o;
}

// ---------------- launch --------------------------------------------------
extern "C" void kernel_launch(void* const* d_in, const int* in_sizes, int n_in,
                              void* d_out, int out_size) {
    (void)in_sizes; (void)n_in; (void)out_size;
    const float* x  = (const float*)d_in[0];
    const void*  ei = d_in[1];
    const float* ea = (const float*)d_in[2];
    const float* Wu = (const float*)d_in[3];
    const float* bu = (const float*)d_in[4];
    const float* Wv = (const float*)d_in[5];
    const float* bv = (const float*)d_in[6];
    const float* WA = (const float*)d_in[7];
    const float* bA = (const float*)d_in[8];
    const float* WB = (const float*)d_in[9];
    const float* bB = (const float*)d_in[10];
    const float* WC = (const float*)d_in[11];
    const float* bC = (const float*)d_in[12];
    const float* gn_g = (const float*)d_in[13];
    const float* gn_b = (const float*)d_in[14];
    const float* ge_g = (const float*)d_in[15];
    const float* ge_b = (const float*)d_in[16];

    float* out   = (float*)d_out;
    float* out_x = out;
    float* out_e = out + (size_t)Nn * Dd;

    const int smem_node = (128 * 130 + 32 * 128) * 4;          // 82944 B
    const int smem_edge = (128 * 130 + 32 * 128) * 4 + 64 * 4; // 83200 B
    cudaFuncSetAttribute(node_gemm_kernel, cudaFuncAttributeMaxDynamicSharedMemorySize, 86016);
    cudaFuncSetAttribute(edge_gemm_kernel, cudaFuncAttributeMaxDynamicSharedMemorySize, 86016);

    detect_kernel<<<1, 256>>>((const unsigned*)ei);
    zero_kernel<<<2048, 256>>>();
    node_gemm_kernel<<<dim3((Nn + 31) / 32, 4), 128, smem_node>>>(
        x, Wu, bu, Wv, bv, WB, bB, WC, bC);
    edge_gemm_kernel<<<Ee / 32, 128, smem_edge>>>(ea, ei, WA, bA);
    finalize_kernel<<<1, 128>>>(0, 1.0f / (float)Ee);
    edge_pass2_kernel<<<(Ee + 7) / 8, 256>>>(ea, ei, ge_g, ge_b, out_e);
    node_stats_kernel<<<(Nn + 63) / 64, 128>>>();
    finalize_kernel<<<1, 128>>>(1, 1.0f / (float)Nn);
    node_out_kernel<<<(Nn * 32 + 255) / 256, 256>>>(x, gn_g, gn_b, out_x);
}

// round 5
// speedup vs baseline: 1.6911x; 1.6911x over previous
#include <cuda_runtime.h>
#include <cuda_bf16.h>
#include <cstdint>

#define Nn 50000
#define Ee 640000
#define Dd 128

// ---------------- device scratch ------------------------------------------
__device__ float g_U[Nn * 128];
__device__ float g_B[Nn * 128];
__device__ float g_CV[Nn * 256];                 // [Cx | Vx]
__device__ float g_edge_in[(size_t)Ee * 128];
__device__ float g_agg[Nn * 128];
__device__ float g_stats[1024];
__device__ int g_is64;

// ---------------- smem layout (bytes) --------------------------------------
#define SB_BIAS 0
#define SB_IDX  512
#define SB_STAT 1536
#define SB_AH   2560
#define SB_AL   37376
#define SB_WH   72192
#define SB_WL   107008
#define S_SIZE  141824
#define ASTRIDE 136   // uint16 elements per row (128 + 8 pad)

// ---------------- mma.sync bf16 helper --------------------------------------
__device__ __forceinline__ void mma_bf16(float* d, uint32_t a0, uint32_t a1,
                                         uint32_t a2, uint32_t a3,
                                         uint32_t b0, uint32_t b1) {
    asm volatile("mma.sync.aligned.m16n8k16.row.col.f32.bf16.bf16.f32 "
        "{%0,%1,%2,%3}, {%4,%5,%6,%7}, {%8,%9}, {%0,%1,%2,%3};"
        : "+f"(d[0]), "+f"(d[1]), "+f"(d[2]), "+f"(d[3])
        : "r"(a0), "r"(a1), "r"(a2), "r"(a3), "r"(b0), "r"(b1));
}

// 3-term hi/lo warp GEMM: acc[nt][4] = warp's 16x128 slice of A(128x128)@W^T
__device__ __forceinline__ void warp_gemm(const uint16_t* __restrict__ Ah,
                                          const uint16_t* __restrict__ Al,
                                          const uint16_t* __restrict__ Wh,
                                          const uint16_t* __restrict__ Wl,
                                          int wid, int lane, float acc[16][4]) {
    const int gid = lane >> 2, tig = lane & 3;
    const int m0 = wid * 16;
#pragma unroll
    for (int nt = 0; nt < 16; nt++) {
        acc[nt][0] = 0.f; acc[nt][1] = 0.f; acc[nt][2] = 0.f; acc[nt][3] = 0.f;
    }
#pragma unroll
    for (int term = 0; term < 3; term++) {
        const uint16_t* A = (term == 2) ? Al : Ah;
        const uint16_t* W = (term == 1) ? Wl : Wh;
        const uint16_t* arow = A + (m0 + gid) * ASTRIDE + tig * 2;
        const uint16_t* wrow = W + gid * ASTRIDE + tig * 2;
#pragma unroll
        for (int ks = 0; ks < 8; ks++) {
            const int k0 = ks * 16;
            uint32_t a0 = *(const uint32_t*)(arow + k0);
            uint32_t a1 = *(const uint32_t*)(arow + 8 * ASTRIDE + k0);
            uint32_t a2 = *(const uint32_t*)(arow + k0 + 8);
            uint32_t a3 = *(const uint32_t*)(arow + 8 * ASTRIDE + k0 + 8);
#pragma unroll
            for (int nt = 0; nt < 16; nt++) {
                uint32_t b0 = *(const uint32_t*)(wrow + nt * 8 * ASTRIDE + k0);
                uint32_t b1 = *(const uint32_t*)(wrow + nt * 8 * ASTRIDE + k0 + 8);
                mma_bf16(acc[nt], a0, a1, a2, a3, b0, b1);
            }
        }
    }
}

// fp32 [rows,128] tile -> hi/lo bf16 planes in smem (256 threads)
__device__ __forceinline__ void cvt_tile(uint16_t* __restrict__ hi_dst,
                                         uint16_t* __restrict__ lo_dst,
                                         const float* __restrict__ src,
                                         int valid_rows) {
    for (int idx = threadIdx.x; idx < 4096; idx += 256) {
        int row = idx >> 5, k4 = (idx & 31) << 2;
        float4 v = (row < valid_rows) ? ((const float4*)src)[idx]
                                      : make_float4(0.f, 0.f, 0.f, 0.f);
        __nv_bfloat16 h0 = __float2bfloat16(v.x), h1 = __float2bfloat16(v.y);
        __nv_bfloat16 h2 = __float2bfloat16(v.z), h3 = __float2bfloat16(v.w);
        __nv_bfloat16 l0 = __float2bfloat16(v.x - __bfloat162float(h0));
        __nv_bfloat16 l1 = __float2bfloat16(v.y - __bfloat162float(h1));
        __nv_bfloat16 l2 = __float2bfloat16(v.z - __bfloat162float(h2));
        __nv_bfloat16 l3 = __float2bfloat16(v.w - __bfloat162float(h3));
        uint2 hi, lo;
        hi.x = ((uint32_t)__bfloat16_as_ushort(h1) << 16) | __bfloat16_as_ushort(h0);
        hi.y = ((uint32_t)__bfloat16_as_ushort(h3) << 16) | __bfloat16_as_ushort(h2);
        lo.x = ((uint32_t)__bfloat16_as_ushort(l1) << 16) | __bfloat16_as_ushort(l0);
        lo.y = ((uint32_t)__bfloat16_as_ushort(l3) << 16) | __bfloat16_as_ushort(l2);
        *(uint2*)(hi_dst + row * ASTRIDE + k4) = hi;
        *(uint2*)(lo_dst + row * ASTRIDE + k4) = lo;
    }
}

__device__ __forceinline__ int ld_idx(const void* p, size_t i, int is64) {
    return is64 ? (int)((const long long*)p)[i] : ((const int*)p)[i];
}

// ---------------- small kernels ----------------------------------------------
__global__ void detect_kernel(const unsigned* __restrict__ w) {
    __shared__ int sflag;
    if (threadIdx.x == 0) sflag = 0;
    __syncthreads();
    unsigned v = 0;
    for (int i = threadIdx.x; i < 2048; i += blockDim.x) v |= w[2 * i + 1];
    if (v) atomicOr(&sflag, 1);
    __syncthreads();
    if (threadIdx.x == 0) g_is64 = sflag ? 0 : 1;
}
__global__ void zero_kernel() {
    int i = blockIdx.x * blockDim.x + threadIdx.x;
    const int total = Nn * 128;
    for (int k = i; k < total; k += gridDim.x * blockDim.x) g_agg[k] = 0.f;
    if (i < 1024) g_stats[i] = 0.f;
}

// ---------------- node GEMMs: one (tile, matrix) per block --------------------
__global__ void __launch_bounds__(256, 1) node_mma_kernel(
        const float* __restrict__ x,
        const float* __restrict__ Wu, const float* __restrict__ bu,
        const float* __restrict__ Wv, const float* __restrict__ bv,
        const float* __restrict__ WB, const float* __restrict__ bB,
        const float* __restrict__ WC, const float* __restrict__ bC) {
    extern __shared__ char sm[];
    uint16_t* Ah = (uint16_t*)(sm + SB_AH);
    uint16_t* Al = (uint16_t*)(sm + SB_AL);
    uint16_t* Wh = (uint16_t*)(sm + SB_WH);
    uint16_t* Wl = (uint16_t*)(sm + SB_WL);
    float* sb = (float*)(sm + SB_BIAS);
    const int tid = threadIdx.x, wid = tid >> 5, lane = tid & 31;
    const int which = blockIdx.y;
    const float* W = (which == 0) ? Wu : (which == 1) ? Wv : (which == 2) ? WB : WC;
    const float* bias = (which == 0) ? bu : (which == 1) ? bv : (which == 2) ? bB : bC;
    if (tid < 128) sb[tid] = bias[tid];
    const int n0 = blockIdx.x * 128;
    int valid = Nn - n0; if (valid > 128) valid = 128;
    cvt_tile(Ah, Al, x + (size_t)n0 * 128, valid);
    cvt_tile(Wh, Wl, W, 128);
    __syncthreads();

    float acc[16][4];
    warp_gemm(Ah, Al, Wh, Wl, wid, lane, acc);

    const int gid = lane >> 2, tig = lane & 3;
    const int r0 = n0 + wid * 16 + gid;
    float* dst0;
    int rstride;
    if (which == 0)      { dst0 = g_U;        rstride = 128; }
    else if (which == 1) { dst0 = g_CV + 128; rstride = 256; }
    else if (which == 2) { dst0 = g_B;        rstride = 128; }
    else                 { dst0 = g_CV;       rstride = 256; }
#pragma unroll
    for (int nt = 0; nt < 16; nt++) {
        int c = nt * 8 + tig * 2;
        float2 bb = *(const float2*)(sb + c);
        if (r0 < Nn) {
            float2 o = make_float2(acc[nt][0] + bb.x, acc[nt][1] + bb.y);
            *(float2*)(dst0 + (size_t)r0 * rstride + c) = o;
        }
        if (r0 + 8 < Nn) {
            float2 o = make_float2(acc[nt][2] + bb.x, acc[nt][3] + bb.y);
            *(float2*)(dst0 + (size_t)(r0 + 8) * rstride + c) = o;
        }
    }
}

// ---------------- edge pass 1: GEMM + gathers + edge_in + BN stats ------------
__global__ void __launch_bounds__(256, 1) edge1_kernel(
        const float* __restrict__ ea, const void* __restrict__ eidx,
        const float* __restrict__ WA, const float* __restrict__ bA) {
    extern __shared__ char sm[];
    uint16_t* Ah = (uint16_t*)(sm + SB_AH);
    uint16_t* Al = (uint16_t*)(sm + SB_AL);
    uint16_t* Wh = (uint16_t*)(sm + SB_WH);
    uint16_t* Wl = (uint16_t*)(sm + SB_WL);
    float* sb = (float*)(sm + SB_BIAS);
    int* sidx = (int*)(sm + SB_IDX);
    float* sstat = (float*)(sm + SB_STAT);
    const int tid = threadIdx.x, wid = tid >> 5, lane = tid & 31;
    const int is64 = g_is64;
    const size_t t = blockIdx.x;

    if (tid < 128) sb[tid] = bA[tid];
    sstat[tid] = 0.f;
    cvt_tile(Ah, Al, ea + t * 16384, 128);
    cvt_tile(Wh, Wl, WA, 128);
    if (tid < 128) sidx[tid] = ld_idx(eidx, t * 128 + tid, is64);
    else           sidx[tid] = ld_idx(eidx, (size_t)Ee + t * 128 + (tid - 128), is64);
    __syncthreads();

    float acc[16][4];
    warp_gemm(Ah, Al, Wh, Wl, wid, lane, acc);

    const int gid = lane >> 2, tig = lane & 3;
    const int rl0 = wid * 16 + gid, rl1 = rl0 + 8;
    const int ridx0 = sidx[rl0], cidx0 = sidx[128 + rl0];
    const int ridx1 = sidx[rl1], cidx1 = sidx[128 + rl1];
    float* e0 = g_edge_in + (t * 128 + rl0) * 128;
    float* e1 = g_edge_in + (t * 128 + rl1) * 128;
#pragma unroll
    for (int nt = 0; nt < 16; nt++) {
        int c = nt * 8 + tig * 2;
        float2 ba = *(const float2*)(sb + c);
        float2 B0 = *(const float2*)(g_B + (size_t)ridx0 * 128 + c);
        float2 C0 = *(const float2*)(g_CV + (size_t)cidx0 * 256 + c);
        float2 B1 = *(const float2*)(g_B + (size_t)ridx1 * 128 + c);
        float2 C1 = *(const float2*)(g_CV + (size_t)cidx1 * 256 + c);
        float v0x = acc[nt][0] + ba.x + B0.x + C0.x;
        float v0y = acc[nt][1] + ba.y + B0.y + C0.y;
        float v1x = acc[nt][2] + ba.x + B1.x + C1.x;
        float v1y = acc[nt][3] + ba.y + B1.y + C1.y;
        *(float2*)(e0 + c) = make_float2(v0x, v0y);
        *(float2*)(e1 + c) = make_float2(v1x, v1y);
        float p1 = v0x + v1x, p2 = v0y + v1y;
        float q1 = fmaf(v0x, v0x, v1x * v1x);
        float q2 = fmaf(v0y, v0y, v1y * v1y);
#pragma unroll
        for (int o = 4; o < 32; o <<= 1) {
            p1 += __shfl_xor_sync(0xFFFFFFFFu, p1, o);
            p2 += __shfl_xor_sync(0xFFFFFFFFu, p2, o);
            q1 += __shfl_xor_sync(0xFFFFFFFFu, q1, o);
            q2 += __shfl_xor_sync(0xFFFFFFFFu, q2, o);
        }
        if (gid == 0) {
            atomicAdd(&sstat[c], p1);
            atomicAdd(&sstat[c + 1], p2);
            atomicAdd(&sstat[128 + c], q1);
            atomicAdd(&sstat[128 + c + 1], q2);
        }
    }
    __syncthreads();
    atomicAdd(&g_stats[tid], sstat[tid]);
}

// ---------------- finalize BN stats (0=edge, 1=node) --------------------------
__global__ void finalize_kernel(int which, float inv) {
    int f = threadIdx.x;
    float s1 = g_stats[which * 256 + f];
    float s2 = g_stats[which * 256 + 128 + f];
    float mean = s1 * inv;
    float var = fmaxf(s2 * inv - mean * mean, 0.f);
    g_stats[512 + which * 256 + f] = mean;
    g_stats[512 + which * 256 + 128 + f] = rsqrtf(var + 1e-5f);
}

// ---------------- edge pass 2 ---------------------------------------------------
__global__ void edge_pass2_kernel(const float* __restrict__ ea, const void* __restrict__ eidx,
                                  const float* __restrict__ gam, const float* __restrict__ bet,
                                  float* __restrict__ out_e) {
    int e = blockIdx.x * 8 + (threadIdx.x >> 5);
    if (e >= Ee) return;
    int c = (threadIdx.x & 31) * 4;
    int row, col;
    if (g_is64) {
        const long long* p = (const long long*)eidx;
        row = (int)p[e];
        col = (int)p[(size_t)Ee + e];
    } else {
        const int* p = (const int*)eidx;
        row = p[e];
        col = p[Ee + e];
    }
    size_t base = (size_t)e * 128 + c;
    float4 ein = *(const float4*)(g_edge_in + base);
    float4 mu = *(const float4*)(g_stats + 512 + c);
    float4 rs = *(const float4*)(g_stats + 640 + c);
    float4 gm = __ldg((const float4*)(gam + c));
    float4 bt = __ldg((const float4*)(bet + c));
    float4 a4 = __ldg((const float4*)(ea + base));
    float4 eo;
    eo.x = a4.x + fmaxf(gm.x * (ein.x - mu.x) * rs.x + bt.x, 0.f);
    eo.y = a4.y + fmaxf(gm.y * (ein.y - mu.y) * rs.y + bt.y, 0.f);
    eo.z = a4.z + fmaxf(gm.z * (ein.z - mu.z) * rs.z + bt.z, 0.f);
    eo.w = a4.w + fmaxf(gm.w * (ein.w - mu.w) * rs.w + bt.w, 0.f);
    *(float4*)(out_e + base) = eo;

    float4 v4 = *(const float4*)(g_CV + (size_t)col * 256 + 128 + c);
    float mx = v4.x / (1.f + __expf(-eo.x));
    float my = v4.y / (1.f + __expf(-eo.y));
    float mz = v4.z / (1.f + __expf(-eo.z));
    float mw = v4.w / (1.f + __expf(-eo.w));
    float* dst = g_agg + (size_t)row * 128 + c;
    asm volatile("red.global.add.v4.f32 [%0], {%1, %2, %3, %4};"
                 :: "l"(dst), "f"(mx), "f"(my), "f"(mz), "f"(mw) : "memory");
}

// ---------------- node stats / output -------------------------------------------
__global__ void node_stats_kernel() {
    int f = threadIdx.x;
    int n0 = blockIdx.x * 64;
    float s1 = 0.f, s2 = 0.f;
    for (int r = 0; r < 64; r++) {
        int n = n0 + r;
        if (n < Nn) {
            float v = g_U[(size_t)n * 128 + f] + g_agg[(size_t)n * 128 + f];
            s1 += v;
            s2 += v * v;
        }
    }
    atomicAdd(&g_stats[256 + f], s1);
    atomicAdd(&g_stats[384 + f], s2);
}
__global__ void node_out_kernel(const float* __restrict__ x, const float* __restrict__ gam,
                                const float* __restrict__ bet, float* __restrict__ out_x) {
    int i = blockIdx.x * blockDim.x + threadIdx.x;
    if (i >= Nn * 32) return;
    int c = (i & 31) * 4;
    size_t base = (size_t)i * 4;
    float4 u = *(const float4*)(g_U + base);
    float4 a = *(const float4*)(g_agg + base);
    float4 mu = *(const float4*)(g_stats + 768 + c);
    float4 rs = *(const float4*)(g_stats + 896 + c);
    float4 gm = __ldg((const float4*)(gam + c));
    float4 bt = __ldg((const float4*)(bet + c));
    float4 xv = __ldg((const float4*)(x + base));
    float4 o;
    o.x = xv.x + fmaxf(gm.x * ((u.x + a.x) - mu.x) * rs.x + bt.x, 0.f);
    o.y = xv.y + fmaxf(gm.y * ((u.y + a.y) - mu.y) * rs.y + bt.y, 0.f);
    o.z = xv.z + fmaxf(gm.z * ((u.z + a.z) - mu.z) * rs.z + bt.z, 0.f);
    o.w = xv.w + fmaxf(gm.w * ((u.w + a.w) - mu.w) * rs.w + bt.w, 0.f);
    *(float4*)(out_x + base) = o;
}

// ---------------- launch ----------------------------------------------------------
extern "C" void kernel_launch(void* const* d_in, const int* in_sizes, int n_in,
                              void* d_out, int out_size) {
    (void)in_sizes; (void)n_in; (void)out_size;
    const float* x  = (const float*)d_in[0];
    const void*  ei = d_in[1];
    const float* ea = (const float*)d_in[2];
    const float* Wu = (const float*)d_in[3];
    const float* bu = (const float*)d_in[4];
    const float* Wv = (const float*)d_in[5];
    const float* bv = (const float*)d_in[6];
    const float* WA = (const float*)d_in[7];
    const float* bA = (const float*)d_in[8];
    const float* WB = (const float*)d_in[9];
    const float* bB = (const float*)d_in[10];
    const float* WC = (const float*)d_in[11];
    const float* bC = (const float*)d_in[12];
    const float* gn_g = (const float*)d_in[13];
    const float* gn_b = (const float*)d_in[14];
    const float* ge_g = (const float*)d_in[15];
    const float* ge_b = (const float*)d_in[16];

    float* out   = (float*)d_out;
    float* out_x = out;
    float* out_e = out + (size_t)Nn * Dd;

    cudaFuncSetAttribute(node_mma_kernel, cudaFuncAttributeMaxDynamicSharedMemorySize, S_SIZE);
    cudaFuncSetAttribute(edge1_kernel, cudaFuncAttributeMaxDynamicSharedMemorySize, S_SIZE);

    detect_kernel<<<1, 256>>>((const unsigned*)ei);
    zero_kernel<<<2048, 256>>>();
    node_mma_kernel<<<dim3((Nn + 127) / 128, 4), 256, S_SIZE>>>(
        x, Wu, bu, Wv, bv, WB, bB, WC, bC);
    edge1_kernel<<<Ee / 128, 256, S_SIZE>>>(ea, ei, WA, bA);
    finalize_kernel<<<1, 128>>>(0, 1.0f / (float)Ee);
    edge_pass2_kernel<<<(Ee + 7) / 8, 256>>>(ea, ei, ge_g, ge_b, out_e);
    node_stats_kernel<<<(Nn + 63) / 64, 128>>>();
    finalize_kernel<<<1, 128>>>(1, 1.0f / (float)Nn);
    node_out_kernel<<<(Nn * 32 + 255) / 256, 256>>>(x, gn_g, gn_b, out_x);
}

// round 6
// speedup vs baseline: 2.1443x; 1.2680x over previous
#include <cuda_runtime.h>
#include <cuda_bf16.h>
#include <cstdint>

#define Nn 50000
#define Ee 640000
#define Dd 128

#define ASTRIDE 136              // uint16 elems per row (128 + 8 pad)
#define ROWB    (ASTRIDE * 2)    // 272 bytes per row
#define WPLANE  (128 * ASTRIDE)  // uint16 elems per W plane

// ---------------- device scratch ------------------------------------------
__device__ float g_U[Nn * 128];
__device__ float g_B[Nn * 128];
__device__ float g_CV[Nn * 256];                 // [Cx | Vx]
__device__ float g_edge_in[(size_t)Ee * 128];
__device__ float g_agg[Nn * 128];
__device__ float g_stats[1024];
__device__ __align__(16) uint16_t g_Wp[5 * 2 * WPLANE]; // pre-split W hi/lo planes
__device__ int g_is64;

// ---------------- smem layout (bytes) --------------------------------------
#define SB_BIAS 0
#define SB_IDX  512
#define SB_STAT 1536
#define SB_AH   2560
#define SB_AL   19968           // +64*272
#define SB_WH   37376
#define SB_WL   72192           // +128*272
#define S_SIZE  107008

// ---------------- PTX helpers ------------------------------------------------
__device__ __forceinline__ uint32_t smem_u32(const void* p) {
    uint32_t a;
    asm("{ .reg .u64 t; cvta.to.shared.u64 t, %1; cvt.u32.u64 %0, t; }" : "=r"(a) : "l"(p));
    return a;
}
__device__ __forceinline__ void ldsm4(uint32_t& r0, uint32_t& r1, uint32_t& r2,
                                      uint32_t& r3, uint32_t addr) {
    asm volatile("ldmatrix.sync.aligned.m8n8.x4.shared.b16 {%0,%1,%2,%3}, [%4];"
                 : "=r"(r0), "=r"(r1), "=r"(r2), "=r"(r3) : "r"(addr));
}
__device__ __forceinline__ void mma_bf16(float* d, uint32_t a0, uint32_t a1,
                                         uint32_t a2, uint32_t a3,
                                         uint32_t b0, uint32_t b1) {
    asm volatile("mma.sync.aligned.m16n8k16.row.col.f32.bf16.bf16.f32 "
        "{%0,%1,%2,%3}, {%4,%5,%6,%7}, {%8,%9}, {%0,%1,%2,%3};"
        : "+f"(d[0]), "+f"(d[1]), "+f"(d[2]), "+f"(d[3])
        : "r"(a0), "r"(a1), "r"(a2), "r"(a3), "r"(b0), "r"(b1));
}

// 3-term hi/lo warp GEMM on a 64x128 A tile: warp computes 16 rows x 64 cols.
// acc[j][4], j = local n-tile (8 cols each).
__device__ __forceinline__ void warp_gemm64(uint32_t ah, uint32_t al,
                                            uint32_t wh, uint32_t wl,
                                            int wid, int lane, float acc[8][4]) {
    const int m0 = (wid & 3) * 16;
    const int nb = (wid >> 2) * 64;
#pragma unroll
    for (int j = 0; j < 8; j++) {
        acc[j][0] = 0.f; acc[j][1] = 0.f; acc[j][2] = 0.f; acc[j][3] = 0.f;
    }
    // ldmatrix lane->address maps (see mma fragment layout)
    const uint32_t aoffs = (uint32_t)(m0 + (lane & 15)) * ROWB + ((lane >> 4) << 4);
    const uint32_t woffs = (uint32_t)(nb + (lane & 7) + ((lane >> 4) << 3)) * ROWB
                         + (((lane >> 3) & 1) << 4);
#pragma unroll
    for (int term = 0; term < 3; term++) {
        const uint32_t ab = ((term == 2) ? al : ah) + aoffs;
        const uint32_t wb = ((term == 1) ? wl : wh) + woffs;
#pragma unroll
        for (int ks = 0; ks < 8; ks++) {
            uint32_t a0, a1, a2, a3;
            ldsm4(a0, a1, a2, a3, ab + ks * 32);
#pragma unroll
            for (int ntp = 0; ntp < 4; ntp++) {
                uint32_t b0, b1, b2, b3;
                ldsm4(b0, b1, b2, b3, wb + (uint32_t)ntp * 16 * ROWB + ks * 32);
                mma_bf16(acc[2 * ntp],     a0, a1, a2, a3, b0, b1);
                mma_bf16(acc[2 * ntp + 1], a0, a1, a2, a3, b2, b3);
            }
        }
    }
}

// fp32 [<=64,128] tile -> hi/lo bf16 planes in smem (256 threads)
__device__ __forceinline__ void cvt64(uint16_t* __restrict__ hi_dst,
                                      uint16_t* __restrict__ lo_dst,
                                      const float* __restrict__ src,
                                      int valid_rows) {
    for (int idx = threadIdx.x; idx < 2048; idx += 256) {
        int row = idx >> 5, k4 = (idx & 31) << 2;
        float4 v = (row < valid_rows) ? ((const float4*)src)[idx]
                                      : make_float4(0.f, 0.f, 0.f, 0.f);
        __nv_bfloat16 h0 = __float2bfloat16(v.x), h1 = __float2bfloat16(v.y);
        __nv_bfloat16 h2 = __float2bfloat16(v.z), h3 = __float2bfloat16(v.w);
        __nv_bfloat16 l0 = __float2bfloat16(v.x - __bfloat162float(h0));
        __nv_bfloat16 l1 = __float2bfloat16(v.y - __bfloat162float(h1));
        __nv_bfloat16 l2 = __float2bfloat16(v.z - __bfloat162float(h2));
        __nv_bfloat16 l3 = __float2bfloat16(v.w - __bfloat162float(h3));
        uint2 hi, lo;
        hi.x = ((uint32_t)__bfloat16_as_ushort(h1) << 16) | __bfloat16_as_ushort(h0);
        hi.y = ((uint32_t)__bfloat16_as_ushort(h3) << 16) | __bfloat16_as_ushort(h2);
        lo.x = ((uint32_t)__bfloat16_as_ushort(l1) << 16) | __bfloat16_as_ushort(l0);
        lo.y = ((uint32_t)__bfloat16_as_ushort(l3) << 16) | __bfloat16_as_ushort(l2);
        *(uint2*)(hi_dst + row * ASTRIDE + k4) = hi;
        *(uint2*)(lo_dst + row * ASTRIDE + k4) = lo;
    }
}
// copy pre-split W planes (hi+lo contiguous, 69632 B) global -> smem
__device__ __forceinline__ void copyW(char* dst, int mtx) {
    const uint4* s = (const uint4*)(g_Wp + (size_t)mtx * 2 * WPLANE);
    uint4* d = (uint4*)dst;
    for (int i = threadIdx.x; i < 4352; i += 256) d[i] = s[i];
}
__device__ __forceinline__ int ld_idx(const void* p, size_t i, int is64) {
    return is64 ? (int)((const long long*)p)[i] : ((const int*)p)[i];
}

// ---------------- small kernels -----------------------------------------------
__global__ void detect_kernel(const unsigned* __restrict__ w) {
    __shared__ int sflag;
    if (threadIdx.x == 0) sflag = 0;
    __syncthreads();
    unsigned v = 0;
    for (int i = threadIdx.x; i < 2048; i += blockDim.x) v |= w[2 * i + 1];
    if (v) atomicOr(&sflag, 1);
    __syncthreads();
    if (threadIdx.x == 0) g_is64 = sflag ? 0 : 1;
}
__global__ void zero_kernel() {
    int i = blockIdx.x * blockDim.x + threadIdx.x;
    const int total = Nn * 128;
    for (int k = i; k < total; k += gridDim.x * blockDim.x) g_agg[k] = 0.f;
    if (i < 1024) g_stats[i] = 0.f;
}
__global__ void prep_w_kernel(const float* __restrict__ Wu, const float* __restrict__ Wv,
                              const float* __restrict__ WB, const float* __restrict__ WC,
                              const float* __restrict__ WA) {
    int mtx = blockIdx.x;
    const float* W = (mtx == 0) ? Wu : (mtx == 1) ? Wv : (mtx == 2) ? WB : (mtx == 3) ? WC : WA;
    uint16_t* hi = g_Wp + (size_t)mtx * 2 * WPLANE;
    uint16_t* lo = hi + WPLANE;
    for (int idx = threadIdx.x; idx < 16384; idx += blockDim.x) {
        int f = idx >> 7, k = idx & 127;
        float w = W[idx];
        __nv_bfloat16 h = __float2bfloat16(w);
        __nv_bfloat16 l = __float2bfloat16(w - __bfloat162float(h));
        hi[f * ASTRIDE + k] = __bfloat16_as_ushort(h);
        lo[f * ASTRIDE + k] = __bfloat16_as_ushort(l);
    }
}

// ---------------- node GEMMs: one (64-row tile, matrix) per block ---------------
__global__ void __launch_bounds__(256, 2) node_mma_kernel(
        const float* __restrict__ x, const float* __restrict__ bu,
        const float* __restrict__ bv, const float* __restrict__ bB,
        const float* __restrict__ bC) {
    extern __shared__ char sm[];
    uint32_t smb = smem_u32(sm);
    const int tid = threadIdx.x, wid = tid >> 5, lane = tid & 31;
    const int which = blockIdx.y;
    float* sb = (float*)(sm + SB_BIAS);
    const float* bias = (which == 0) ? bu : (which == 1) ? bv : (which == 2) ? bB : bC;
    if (tid < 128) sb[tid] = bias[tid];
    const int n0 = blockIdx.x * 64;
    int valid = Nn - n0; if (valid > 64) valid = 64;
    cvt64((uint16_t*)(sm + SB_AH), (uint16_t*)(sm + SB_AL), x + (size_t)n0 * 128, valid);
    copyW(sm + SB_WH, which);
    __syncthreads();

    float acc[8][4];
    warp_gemm64(smb + SB_AH, smb + SB_AL, smb + SB_WH, smb + SB_WL, wid, lane, acc);

    const int gid = lane >> 2, tig = lane & 3;
    const int m0 = (wid & 3) * 16, nb = (wid >> 2) * 64;
    const int r0 = n0 + m0 + gid;
    float* dst0;
    int rstride;
    if (which == 0)      { dst0 = g_U;        rstride = 128; }
    else if (which == 1) { dst0 = g_CV + 128; rstride = 256; }
    else if (which == 2) { dst0 = g_B;        rstride = 128; }
    else                 { dst0 = g_CV;       rstride = 256; }
#pragma unroll
    for (int j = 0; j < 8; j++) {
        int c = nb + j * 8 + tig * 2;
        float2 bb = *(const float2*)(sb + c);
        if (r0 < Nn)
            *(float2*)(dst0 + (size_t)r0 * rstride + c) =
                make_float2(acc[j][0] + bb.x, acc[j][1] + bb.y);
        if (r0 + 8 < Nn)
            *(float2*)(dst0 + (size_t)(r0 + 8) * rstride + c) =
                make_float2(acc[j][2] + bb.x, acc[j][3] + bb.y);
    }
}

// ---------------- edge pass 1: GEMM + gathers + edge_in + BN stats ---------------
__global__ void __launch_bounds__(256, 2) edge1_kernel(
        const float* __restrict__ ea, const void* __restrict__ eidx,
        const float* __restrict__ bA) {
    extern __shared__ char sm[];
    uint32_t smb = smem_u32(sm);
    const int tid = threadIdx.x, wid = tid >> 5, lane = tid & 31;
    const int is64 = g_is64;
    const size_t t = blockIdx.x;
    float* sb = (float*)(sm + SB_BIAS);
    int* sidx = (int*)(sm + SB_IDX);
    float* sstat = (float*)(sm + SB_STAT);

    if (tid < 128) sb[tid] = bA[tid];
    sstat[tid] = 0.f;
    cvt64((uint16_t*)(sm + SB_AH), (uint16_t*)(sm + SB_AL), ea + t * 8192, 64);
    copyW(sm + SB_WH, 4);
    if (tid < 64)       sidx[tid] = ld_idx(eidx, t * 64 + tid, is64);
    else if (tid < 128) sidx[tid] = ld_idx(eidx, (size_t)Ee + t * 64 + (tid - 64), is64);
    __syncthreads();

    float acc[8][4];
    warp_gemm64(smb + SB_AH, smb + SB_AL, smb + SB_WH, smb + SB_WL, wid, lane, acc);

    const int gid = lane >> 2, tig = lane & 3;
    const int m0 = (wid & 3) * 16, nb = (wid >> 2) * 64;
    const int rl0 = m0 + gid, rl1 = rl0 + 8;
    const int ridx0 = sidx[rl0], cidx0 = sidx[64 + rl0];
    const int ridx1 = sidx[rl1], cidx1 = sidx[64 + rl1];
    float* e0 = g_edge_in + (t * 64 + rl0) * 128;
    float* e1 = g_edge_in + (t * 64 + rl1) * 128;
#pragma unroll
    for (int j = 0; j < 8; j++) {
        int c = nb + j * 8 + tig * 2;
        float2 ba = *(const float2*)(sb + c);
        float2 B0 = *(const float2*)(g_B + (size_t)ridx0 * 128 + c);
        float2 C0 = *(const float2*)(g_CV + (size_t)cidx0 * 256 + c);
        float2 B1 = *(const float2*)(g_B + (size_t)ridx1 * 128 + c);
        float2 C1 = *(const float2*)(g_CV + (size_t)cidx1 * 256 + c);
        float v0x = acc[j][0] + ba.x + B0.x + C0.x;
        float v0y = acc[j][1] + ba.y + B0.y + C0.y;
        float v1x = acc[j][2] + ba.x + B1.x + C1.x;
        float v1y = acc[j][3] + ba.y + B1.y + C1.y;
        *(float2*)(e0 + c) = make_float2(v0x, v0y);
        *(float2*)(e1 + c) = make_float2(v1x, v1y);
        float p1 = v0x + v1x, p2 = v0y + v1y;
        float q1 = fmaf(v0x, v0x, v1x * v1x);
        float q2 = fmaf(v0y, v0y, v1y * v1y);
#pragma unroll
        for (int o = 4; o < 32; o <<= 1) {
            p1 += __shfl_xor_sync(0xFFFFFFFFu, p1, o);
            p2 += __shfl_xor_sync(0xFFFFFFFFu, p2, o);
            q1 += __shfl_xor_sync(0xFFFFFFFFu, q1, o);
            q2 += __shfl_xor_sync(0xFFFFFFFFu, q2, o);
        }
        if (gid == 0) {
            atomicAdd(&sstat[c], p1);
            atomicAdd(&sstat[c + 1], p2);
            atomicAdd(&sstat[128 + c], q1);
            atomicAdd(&sstat[128 + c + 1], q2);
        }
    }
    __syncthreads();
    atomicAdd(&g_stats[tid], sstat[tid]);
}

// ---------------- finalize BN stats (0=edge, 1=node) -----------------------------
__global__ void finalize_kernel(int which, float inv) {
    int f = threadIdx.x;
    float s1 = g_stats[which * 256 + f];
    float s2 = g_stats[which * 256 + 128 + f];
    float mean = s1 * inv;
    float var = fmaxf(s2 * inv - mean * mean, 0.f);
    g_stats[512 + which * 256 + f] = mean;
    g_stats[512 + which * 256 + 128 + f] = rsqrtf(var + 1e-5f);
}

// ---------------- edge pass 2 ------------------------------------------------------
__global__ void edge_pass2_kernel(const float* __restrict__ ea, const void* __restrict__ eidx,
                                  const float* __restrict__ gam, const float* __restrict__ bet,
                                  float* __restrict__ out_e) {
    int e = blockIdx.x * 8 + (threadIdx.x >> 5);
    if (e >= Ee) return;
    int c = (threadIdx.x & 31) * 4;
    int row, col;
    if (g_is64) {
        const long long* p = (const long long*)eidx;
        row = (int)p[e];
        col = (int)p[(size_t)Ee + e];
    } else {
        const int* p = (const int*)eidx;
        row = p[e];
        col = p[Ee + e];
    }
    size_t base = (size_t)e * 128 + c;
    float4 ein = *(const float4*)(g_edge_in + base);
    float4 mu = *(const float4*)(g_stats + 512 + c);
    float4 rs = *(const float4*)(g_stats + 640 + c);
    float4 gm = __ldg((const float4*)(gam + c));
    float4 bt = __ldg((const float4*)(bet + c));
    float4 a4 = __ldg((const float4*)(ea + base));
    float4 eo;
    eo.x = a4.x + fmaxf(gm.x * (ein.x - mu.x) * rs.x + bt.x, 0.f);
    eo.y = a4.y + fmaxf(gm.y * (ein.y - mu.y) * rs.y + bt.y, 0.f);
    eo.z = a4.z + fmaxf(gm.z * (ein.z - mu.z) * rs.z + bt.z, 0.f);
    eo.w = a4.w + fmaxf(gm.w * (ein.w - mu.w) * rs.w + bt.w, 0.f);
    *(float4*)(out_e + base) = eo;

    float4 v4 = *(const float4*)(g_CV + (size_t)col * 256 + 128 + c);
    float mx = v4.x / (1.f + __expf(-eo.x));
    float my = v4.y / (1.f + __expf(-eo.y));
    float mz = v4.z / (1.f + __expf(-eo.z));
    float mw = v4.w / (1.f + __expf(-eo.w));
    float* dst = g_agg + (size_t)row * 128 + c;
    asm volatile("red.global.add.v4.f32 [%0], {%1, %2, %3, %4};"
                 :: "l"(dst), "f"(mx), "f"(my), "f"(mz), "f"(mw) : "memory");
}

// ---------------- node stats / output ----------------------------------------------
__global__ void node_stats_kernel() {
    int f = threadIdx.x;
    int n0 = blockIdx.x * 64;
    float s1 = 0.f, s2 = 0.f;
    for (int r = 0; r < 64; r++) {
        int n = n0 + r;
        if (n < Nn) {
            float v = g_U[(size_t)n * 128 + f] + g_agg[(size_t)n * 128 + f];
            s1 += v;
            s2 += v * v;
        }
    }
    atomicAdd(&g_stats[256 + f], s1);
    atomicAdd(&g_stats[384 + f], s2);
}
__global__ void node_out_kernel(const float* __restrict__ x, const float* __restrict__ gam,
                                const float* __restrict__ bet, float* __restrict__ out_x) {
    int i = blockIdx.x * blockDim.x + threadIdx.x;
    if (i >= Nn * 32) return;
    int c = (i & 31) * 4;
    size_t base = (size_t)i * 4;
    float4 u = *(const float4*)(g_U + base);
    float4 a = *(const float4*)(g_agg + base);
    float4 mu = *(const float4*)(g_stats + 768 + c);
    float4 rs = *(const float4*)(g_stats + 896 + c);
    float4 gm = __ldg((const float4*)(gam + c));
    float4 bt = __ldg((const float4*)(bet + c));
    float4 xv = __ldg((const float4*)(x + base));
    float4 o;
    o.x = xv.x + fmaxf(gm.x * ((u.x + a.x) - mu.x) * rs.x + bt.x, 0.f);
    o.y = xv.y + fmaxf(gm.y * ((u.y + a.y) - mu.y) * rs.y + bt.y, 0.f);
    o.z = xv.z + fmaxf(gm.z * ((u.z + a.z) - mu.z) * rs.z + bt.z, 0.f);
    o.w = xv.w + fmaxf(gm.w * ((u.w + a.w) - mu.w) * rs.w + bt.w, 0.f);
    *(float4*)(out_x + base) = o;
}

// ---------------- launch --------------------------------------------------------------
extern "C" void kernel_launch(void* const* d_in, const int* in_sizes, int n_in,
                              void* d_out, int out_size) {
    (void)in_sizes; (void)n_in; (void)out_size;
    const float* x  = (const float*)d_in[0];
    const void*  ei = d_in[1];
    const float* ea = (const float*)d_in[2];
    const float* Wu = (const float*)d_in[3];
    const float* bu = (const float*)d_in[4];
    const float* Wv = (const float*)d_in[5];
    const float* bv = (const float*)d_in[6];
    const float* WA = (const float*)d_in[7];
    const float* bA = (const float*)d_in[8];
    const float* WB = (const float*)d_in[9];
    const float* bB = (const float*)d_in[10];
    const float* WC = (const float*)d_in[11];
    const float* bC = (const float*)d_in[12];
    const float* gn_g = (const float*)d_in[13];
    const float* gn_b = (const float*)d_in[14];
    const float* ge_g = (const float*)d_in[15];
    const float* ge_b = (const float*)d_in[16];

    float* out   = (float*)d_out;
    float* out_x = out;
    float* out_e = out + (size_t)Nn * Dd;

    cudaFuncSetAttribute(node_mma_kernel, cudaFuncAttributeMaxDynamicSharedMemorySize, S_SIZE);
    cudaFuncSetAttribute(edge1_kernel, cudaFuncAttributeMaxDynamicSharedMemorySize, S_SIZE);

    detect_kernel<<<1, 256>>>((const unsigned*)ei);
    zero_kernel<<<2048, 256>>>();
    prep_w_kernel<<<5, 256>>>(Wu, Wv, WB, WC, WA);
    node_mma_kernel<<<dim3((Nn + 63) / 64, 4), 256, S_SIZE>>>(x, bu, bv, bB, bC);
    edge1_kernel<<<Ee / 64, 256, S_SIZE>>>(ea, ei, bA);
    finalize_kernel<<<1, 128>>>(0, 1.0f / (float)Ee);
    edge_pass2_kernel<<<(Ee + 7) / 8, 256>>>(ea, ei, ge_g, ge_b, out_e);
    node_stats_kernel<<<(Nn + 63) / 64, 128>>>();
    finalize_kernel<<<1, 128>>>(1, 1.0f / (float)Nn);
    node_out_kernel<<<(Nn * 32 + 255) / 256, 256>>>(x, gn_g, gn_b, out_x);
}

// round 7
// speedup vs baseline: 2.6452x; 1.2336x over previous
#include <cuda_runtime.h>
#include <cuda_bf16.h>
#include <cstdint>

#define Nn 50000
#define Ee 640000
#define Dd 128

#define ASTRIDE 136              // uint16 elems per row (128 + 8 pad)
#define ROWB    (ASTRIDE * 2)    // 272 bytes per row
#define WPLANE  (128 * ASTRIDE)  // uint16 elems per W plane
#define NT_E    (Ee / 32)        // 20000 edge tiles
#define NT_N    ((Nn + 31) / 32) // 1563 node tiles

// ---------------- device scratch ------------------------------------------
__device__ float g_U[Nn * 128];
__device__ float g_B[Nn * 128];
__device__ float g_CV[Nn * 256];                 // [Cx | Vx]
__device__ float g_edge_in[(size_t)Ee * 128];
__device__ float g_agg[Nn * 128];
__device__ float g_stats[1024];
__device__ __align__(16) uint16_t g_Wp[5 * 2 * WPLANE]; // pre-split W hi/lo planes
__device__ int g_is64;

// ---------------- smem layout (bytes) --------------------------------------
#define SB_BIAS 0                 // 512
#define SB_IDX  512               // 2 x 64 ints (double buffered)
#define SB_STAT 1024              // 256 floats
#define SB_A    2048              // 2 buffers x (hi 8704 + lo 8704) = 34816
#define ABUF    17408
#define SB_W    36864             // Wh 34816 + Wl 34816
#define SB_WL   71680
#define S_SIZE  106496

// ---------------- PTX helpers ------------------------------------------------
__device__ __forceinline__ uint32_t smem_u32(const void* p) {
    uint32_t a;
    asm("{ .reg .u64 t; cvta.to.shared.u64 t, %1; cvt.u32.u64 %0, t; }" : "=r"(a) : "l"(p));
    return a;
}
__device__ __forceinline__ void ldsm4(uint32_t& r0, uint32_t& r1, uint32_t& r2,
                                      uint32_t& r3, uint32_t addr) {
    asm volatile("ldmatrix.sync.aligned.m8n8.x4.shared.b16 {%0,%1,%2,%3}, [%4];"
                 : "=r"(r0), "=r"(r1), "=r"(r2), "=r"(r3) : "r"(addr));
}
__device__ __forceinline__ void mma_bf16(float* d, uint32_t a0, uint32_t a1,
                                         uint32_t a2, uint32_t a3,
                                         uint32_t b0, uint32_t b1) {
    asm volatile("mma.sync.aligned.m16n8k16.row.col.f32.bf16.bf16.f32 "
        "{%0,%1,%2,%3}, {%4,%5,%6,%7}, {%8,%9}, {%0,%1,%2,%3};"
        : "+f"(d[0]), "+f"(d[1]), "+f"(d[2]), "+f"(d[3])
        : "r"(a0), "r"(a1), "r"(a2), "r"(a3), "r"(b0), "r"(b1));
}

// 3-term hi/lo warp GEMM on a 32x128 A tile.
// Warp (wid): m-half = wid&1 (16 rows), n-quarter = wid>>1 (32 cols).
__device__ __forceinline__ void warp_gemm32(uint32_t ah, uint32_t al,
                                            uint32_t wh, uint32_t wl,
                                            int wid, int lane, float acc[4][4]) {
    const int m0 = (wid & 1) * 16;
    const int nb = (wid >> 1) * 32;
#pragma unroll
    for (int j = 0; j < 4; j++) {
        acc[j][0] = 0.f; acc[j][1] = 0.f; acc[j][2] = 0.f; acc[j][3] = 0.f;
    }
    const uint32_t aoffs = (uint32_t)(m0 + (lane & 15)) * ROWB + ((lane >> 4) << 4);
    const uint32_t woffs = (uint32_t)(nb + (lane & 7) + ((lane >> 4) << 3)) * ROWB
                         + (((lane >> 3) & 1) << 4);
#pragma unroll
    for (int term = 0; term < 3; term++) {
        const uint32_t ab = ((term == 2) ? al : ah) + aoffs;
        const uint32_t wb = ((term == 1) ? wl : wh) + woffs;
#pragma unroll
        for (int ks = 0; ks < 8; ks++) {
            uint32_t a0, a1, a2, a3;
            ldsm4(a0, a1, a2, a3, ab + ks * 32);
#pragma unroll
            for (int ntp = 0; ntp < 2; ntp++) {
                uint32_t b0, b1, b2, b3;
                ldsm4(b0, b1, b2, b3, wb + (uint32_t)ntp * 16 * ROWB + ks * 32);
                mma_bf16(acc[2 * ntp],     a0, a1, a2, a3, b0, b1);
                mma_bf16(acc[2 * ntp + 1], a0, a1, a2, a3, b2, b3);
            }
        }
    }
}

// prefetch a 32x128 fp32 tile into 4 float4 regs per thread (256 threads)
__device__ __forceinline__ void load_regs(float4* pre, const float* __restrict__ src,
                                          int valid_rows) {
#pragma unroll
    for (int p = 0; p < 4; p++) {
        int idx = p * 256 + threadIdx.x;
        int row = idx >> 5;
        pre[p] = (row < valid_rows) ? ((const float4*)src)[idx]
                                    : make_float4(0.f, 0.f, 0.f, 0.f);
    }
}
// convert prefetched regs -> hi/lo bf16 planes in smem
__device__ __forceinline__ void cvt_store(uint16_t* __restrict__ hi_dst,
                                          uint16_t* __restrict__ lo_dst,
                                          const float4* pre) {
#pragma unroll
    for (int p = 0; p < 4; p++) {
        int idx = p * 256 + threadIdx.x;
        int row = idx >> 5, k4 = (idx & 31) << 2;
        float4 v = pre[p];
        __nv_bfloat16 h0 = __float2bfloat16(v.x), h1 = __float2bfloat16(v.y);
        __nv_bfloat16 h2 = __float2bfloat16(v.z), h3 = __float2bfloat16(v.w);
        __nv_bfloat16 l0 = __float2bfloat16(v.x - __bfloat162float(h0));
        __nv_bfloat16 l1 = __float2bfloat16(v.y - __bfloat162float(h1));
        __nv_bfloat16 l2 = __float2bfloat16(v.z - __bfloat162float(h2));
        __nv_bfloat16 l3 = __float2bfloat16(v.w - __bfloat162float(h3));
        uint2 hi, lo;
        hi.x = ((uint32_t)__bfloat16_as_ushort(h1) << 16) | __bfloat16_as_ushort(h0);
        hi.y = ((uint32_t)__bfloat16_as_ushort(h3) << 16) | __bfloat16_as_ushort(h2);
        lo.x = ((uint32_t)__bfloat16_as_ushort(l1) << 16) | __bfloat16_as_ushort(l0);
        lo.y = ((uint32_t)__bfloat16_as_ushort(l3) << 16) | __bfloat16_as_ushort(l2);
        *(uint2*)(hi_dst + row * ASTRIDE + k4) = hi;
        *(uint2*)(lo_dst + row * ASTRIDE + k4) = lo;
    }
}
__device__ __forceinline__ void copyW(char* dst, int mtx) {
    const uint4* s = (const uint4*)(g_Wp + (size_t)mtx * 2 * WPLANE);
    uint4* d = (uint4*)dst;
    for (int i = threadIdx.x; i < 4352; i += 256) d[i] = s[i];
}
__device__ __forceinline__ int ld_idx(const void* p, size_t i, int is64) {
    return is64 ? (int)((const long long*)p)[i] : ((const int*)p)[i];
}

// ---------------- small kernels -----------------------------------------------
__global__ void detect_kernel(const unsigned* __restrict__ w) {
    __shared__ int sflag;
    if (threadIdx.x == 0) sflag = 0;
    __syncthreads();
    unsigned v = 0;
    for (int i = threadIdx.x; i < 2048; i += blockDim.x) v |= w[2 * i + 1];
    if (v) atomicOr(&sflag, 1);
    __syncthreads();
    if (threadIdx.x == 0) g_is64 = sflag ? 0 : 1;
}
__global__ void zero_kernel() {
    int i = blockIdx.x * blockDim.x + threadIdx.x;
    const int total = Nn * 128;
    for (int k = i; k < total; k += gridDim.x * blockDim.x) g_agg[k] = 0.f;
    if (i < 1024) g_stats[i] = 0.f;
}
__global__ void prep_w_kernel(const float* __restrict__ Wu, const float* __restrict__ Wv,
                              const float* __restrict__ WB, const float* __restrict__ WC,
                              const float* __restrict__ WA) {
    int mtx = blockIdx.x;
    const float* W = (mtx == 0) ? Wu : (mtx == 1) ? Wv : (mtx == 2) ? WB : (mtx == 3) ? WC : WA;
    uint16_t* hi = g_Wp + (size_t)mtx * 2 * WPLANE;
    uint16_t* lo = hi + WPLANE;
    for (int idx = threadIdx.x; idx < 16384; idx += blockDim.x) {
        int f = idx >> 7, k = idx & 127;
        float w = W[idx];
        __nv_bfloat16 h = __float2bfloat16(w);
        __nv_bfloat16 l = __float2bfloat16(w - __bfloat162float(h));
        hi[f * ASTRIDE + k] = __bfloat16_as_ushort(h);
        lo[f * ASTRIDE + k] = __bfloat16_as_ushort(l);
    }
}

// ---------------- node GEMMs: persistent, pipelined -----------------------------
__global__ void __launch_bounds__(256, 2) node_mma_kernel(
        const float* __restrict__ x, const float* __restrict__ bu,
        const float* __restrict__ bv, const float* __restrict__ bB,
        const float* __restrict__ bC) {
    extern __shared__ char sm[];
    uint32_t smb = smem_u32(sm);
    const int tid = threadIdx.x, wid = tid >> 5, lane = tid & 31;
    const int which = blockIdx.y;
    float* sb = (float*)(sm + SB_BIAS);
    const float* bias = (which == 0) ? bu : (which == 1) ? bv : (which == 2) ? bB : bC;
    if (tid < 128) sb[tid] = bias[tid];
    copyW(sm + SB_W, which);

    float* dst0;
    int rstride;
    if (which == 0)      { dst0 = g_U;        rstride = 128; }
    else if (which == 1) { dst0 = g_CV + 128; rstride = 256; }
    else if (which == 2) { dst0 = g_B;        rstride = 128; }
    else                 { dst0 = g_CV;       rstride = 256; }

    const int gid = lane >> 2, tig = lane & 3;
    const int m0 = (wid & 1) * 16, nb = (wid >> 1) * 32;

    float4 pre[4];
    long t = blockIdx.x;
    if (t < NT_N) {
        int v0 = Nn - (int)t * 32; if (v0 > 32) v0 = 32;
        load_regs(pre, x + t * 4096, v0);
    }
    int ib = 0;
    for (; t < NT_N; t += gridDim.x) {
        uint16_t* Ah = (uint16_t*)(sm + SB_A + ib * ABUF);
        uint16_t* Al = Ah + 4352;   // 8704 bytes
        cvt_store(Ah, Al, pre);
        __syncthreads();
        long tn = t + gridDim.x;
        if (tn < NT_N) {
            int vn = Nn - (int)tn * 32; if (vn > 32) vn = 32;
            load_regs(pre, x + tn * 4096, vn);
        }
        float acc[4][4];
        warp_gemm32(smb + SB_A + ib * ABUF, smb + SB_A + ib * ABUF + 8704,
                    smb + SB_W, smb + SB_WL, wid, lane, acc);
        const int r0 = (int)t * 32 + m0 + gid;
#pragma unroll
        for (int j = 0; j < 4; j++) {
            int c = nb + j * 8 + tig * 2;
            float2 bb = *(const float2*)(sb + c);
            if (r0 < Nn)
                *(float2*)(dst0 + (size_t)r0 * rstride + c) =
                    make_float2(acc[j][0] + bb.x, acc[j][1] + bb.y);
            if (r0 + 8 < Nn)
                *(float2*)(dst0 + (size_t)(r0 + 8) * rstride + c) =
                    make_float2(acc[j][2] + bb.x, acc[j][3] + bb.y);
        }
        __syncthreads();
        ib ^= 1;
    }
}

// ---------------- edge pass 1: persistent, pipelined ------------------------------
__global__ void __launch_bounds__(256, 2) edge1_kernel(
        const float* __restrict__ ea, const void* __restrict__ eidx,
        const float* __restrict__ bA) {
    extern __shared__ char sm[];
    uint32_t smb = smem_u32(sm);
    const int tid = threadIdx.x, wid = tid >> 5, lane = tid & 31;
    const int is64 = g_is64;
    float* sb = (float*)(sm + SB_BIAS);
    int* sidx = (int*)(sm + SB_IDX);    // 2 x 64
    float* sstat = (float*)(sm + SB_STAT);
    if (tid < 128) sb[tid] = bA[tid];
    sstat[tid] = 0.f;
    copyW(sm + SB_W, 4);

    const int gid = lane >> 2, tig = lane & 3;
    const int m0 = (wid & 1) * 16, nb = (wid >> 1) * 32;

    float4 pre[4];
    long t = blockIdx.x;
    if (t < NT_E) load_regs(pre, ea + t * 4096, 32);
    int ib = 0;
    for (; t < NT_E; t += gridDim.x) {
        uint16_t* Ah = (uint16_t*)(sm + SB_A + ib * ABUF);
        uint16_t* Al = Ah + 4352;
        cvt_store(Ah, Al, pre);
        if (tid < 32)       sidx[ib * 64 + tid] = ld_idx(eidx, t * 32 + tid, is64);
        else if (tid < 64)  sidx[ib * 64 + tid] =
                                ld_idx(eidx, (size_t)Ee + t * 32 + (tid - 32), is64);
        __syncthreads();
        long tn = t + gridDim.x;
        if (tn < NT_E) load_regs(pre, ea + tn * 4096, 32);
        float acc[4][4];
        warp_gemm32(smb + SB_A + ib * ABUF, smb + SB_A + ib * ABUF + 8704,
                    smb + SB_W, smb + SB_WL, wid, lane, acc);

        const int rl0 = m0 + gid, rl1 = rl0 + 8;
        const int ridx0 = sidx[ib * 64 + rl0], cidx0 = sidx[ib * 64 + 32 + rl0];
        const int ridx1 = sidx[ib * 64 + rl1], cidx1 = sidx[ib * 64 + 32 + rl1];
        float* e0 = g_edge_in + (t * 32 + rl0) * 128;
        float* e1 = g_edge_in + (t * 32 + rl1) * 128;
#pragma unroll
        for (int j = 0; j < 4; j++) {
            int c = nb + j * 8 + tig * 2;
            float2 ba = *(const float2*)(sb + c);
            float2 B0 = *(const float2*)(g_B + (size_t)ridx0 * 128 + c);
            float2 C0 = *(const float2*)(g_CV + (size_t)cidx0 * 256 + c);
            float2 B1 = *(const float2*)(g_B + (size_t)ridx1 * 128 + c);
            float2 C1 = *(const float2*)(g_CV + (size_t)cidx1 * 256 + c);
            float v0x = acc[j][0] + ba.x + B0.x + C0.x;
            float v0y = acc[j][1] + ba.y + B0.y + C0.y;
            float v1x = acc[j][2] + ba.x + B1.x + C1.x;
            float v1y = acc[j][3] + ba.y + B1.y + C1.y;
            *(float2*)(e0 + c) = make_float2(v0x, v0y);
            *(float2*)(e1 + c) = make_float2(v1x, v1y);
            float p1 = v0x + v1x, p2 = v0y + v1y;
            float q1 = fmaf(v0x, v0x, v1x * v1x);
            float q2 = fmaf(v0y, v0y, v1y * v1y);
#pragma unroll
            for (int o = 4; o < 32; o <<= 1) {
                p1 += __shfl_xor_sync(0xFFFFFFFFu, p1, o);
                p2 += __shfl_xor_sync(0xFFFFFFFFu, p2, o);
                q1 += __shfl_xor_sync(0xFFFFFFFFu, q1, o);
                q2 += __shfl_xor_sync(0xFFFFFFFFu, q2, o);
            }
            if (gid == 0) {
                atomicAdd(&sstat[c], p1);
                atomicAdd(&sstat[c + 1], p2);
                atomicAdd(&sstat[128 + c], q1);
                atomicAdd(&sstat[128 + c + 1], q2);
            }
        }
        __syncthreads();
        ib ^= 1;
    }
    __syncthreads();
    atomicAdd(&g_stats[tid], sstat[tid]);
}

// ---------------- finalize BN stats (0=edge, 1=node) --------------------------------
__global__ void finalize_kernel(int which, float inv) {
    int f = threadIdx.x;
    float s1 = g_stats[which * 256 + f];
    float s2 = g_stats[which * 256 + 128 + f];
    float mean = s1 * inv;
    float var = fmaxf(s2 * inv - mean * mean, 0.f);
    g_stats[512 + which * 256 + f] = mean;
    g_stats[512 + which * 256 + 128 + f] = rsqrtf(var + 1e-5f);
}

// ---------------- edge pass 2 ----------------------------------------------------------
__global__ void edge_pass2_kernel(const float* __restrict__ ea, const void* __restrict__ eidx,
                                  const float* __restrict__ gam, const float* __restrict__ bet,
                                  float* __restrict__ out_e) {
    int e = blockIdx.x * 8 + (threadIdx.x >> 5);
    if (e >= Ee) return;
    int c = (threadIdx.x & 31) * 4;
    int row, col;
    if (g_is64) {
        const long long* p = (const long long*)eidx;
        row = (int)p[e];
        col = (int)p[(size_t)Ee + e];
    } else {
        const int* p = (const int*)eidx;
        row = p[e];
        col = p[Ee + e];
    }
    size_t base = (size_t)e * 128 + c;
    float4 ein = *(const float4*)(g_edge_in + base);
    float4 mu = *(const float4*)(g_stats + 512 + c);
    float4 rs = *(const float4*)(g_stats + 640 + c);
    float4 gm = __ldg((const float4*)(gam + c));
    float4 bt = __ldg((const float4*)(bet + c));
    float4 a4 = __ldg((const float4*)(ea + base));
    float4 eo;
    eo.x = a4.x + fmaxf(gm.x * (ein.x - mu.x) * rs.x + bt.x, 0.f);
    eo.y = a4.y + fmaxf(gm.y * (ein.y - mu.y) * rs.y + bt.y, 0.f);
    eo.z = a4.z + fmaxf(gm.z * (ein.z - mu.z) * rs.z + bt.z, 0.f);
    eo.w = a4.w + fmaxf(gm.w * (ein.w - mu.w) * rs.w + bt.w, 0.f);
    *(float4*)(out_e + base) = eo;

    float4 v4 = *(const float4*)(g_CV + (size_t)col * 256 + 128 + c);
    float mx = v4.x / (1.f + __expf(-eo.x));
    float my = v4.y / (1.f + __expf(-eo.y));
    float mz = v4.z / (1.f + __expf(-eo.z));
    float mw = v4.w / (1.f + __expf(-eo.w));
    float* dst = g_agg + (size_t)row * 128 + c;
    asm volatile("red.global.add.v4.f32 [%0], {%1, %2, %3, %4};"
                 :: "l"(dst), "f"(mx), "f"(my), "f"(mz), "f"(mw) : "memory");
}

// ---------------- node stats / output ---------------------------------------------------
__global__ void node_stats_kernel() {
    int f = threadIdx.x;
    int n0 = blockIdx.x * 64;
    float s1 = 0.f, s2 = 0.f;
    for (int r = 0; r < 64; r++) {
        int n = n0 + r;
        if (n < Nn) {
            float v = g_U[(size_t)n * 128 + f] + g_agg[(size_t)n * 128 + f];
            s1 += v;
            s2 += v * v;
        }
    }
    atomicAdd(&g_stats[256 + f], s1);
    atomicAdd(&g_stats[384 + f], s2);
}
__global__ void node_out_kernel(const float* __restrict__ x, const float* __restrict__ gam,
                                const float* __restrict__ bet, float* __restrict__ out_x) {
    int i = blockIdx.x * blockDim.x + threadIdx.x;
    if (i >= Nn * 32) return;
    int c = (i & 31) * 4;
    size_t base = (size_t)i * 4;
    float4 u = *(const float4*)(g_U + base);
    float4 a = *(const float4*)(g_agg + base);
    float4 mu = *(const float4*)(g_stats + 768 + c);
    float4 rs = *(const float4*)(g_stats + 896 + c);
    float4 gm = __ldg((const float4*)(gam + c));
    float4 bt = __ldg((const float4*)(bet + c));
    float4 xv = __ldg((const float4*)(x + base));
    float4 o;
    o.x = xv.x + fmaxf(gm.x * ((u.x + a.x) - mu.x) * rs.x + bt.x, 0.f);
    o.y = xv.y + fmaxf(gm.y * ((u.y + a.y) - mu.y) * rs.y + bt.y, 0.f);
    o.z = xv.z + fmaxf(gm.z * ((u.z + a.z) - mu.z) * rs.z + bt.z, 0.f);
    o.w = xv.w + fmaxf(gm.w * ((u.w + a.w) - mu.w) * rs.w + bt.w, 0.f);
    *(float4*)(out_x + base) = o;
}

// ---------------- launch -----------------------------------------------------------------
extern "C" void kernel_launch(void* const* d_in, const int* in_sizes, int n_in,
                              void* d_out, int out_size) {
    (void)in_sizes; (void)n_in; (void)out_size;
    const float* x  = (const float*)d_in[0];
    const void*  ei = d_in[1];
    const float* ea = (const float*)d_in[2];
    const float* Wu = (const float*)d_in[3];
    const float* bu = (const float*)d_in[4];
    const float* Wv = (const float*)d_in[5];
    const float* bv = (const float*)d_in[6];
    const float* WA = (const float*)d_in[7];
    const float* bA = (const float*)d_in[8];
    const float* WB = (const float*)d_in[9];
    const float* bB = (const float*)d_in[10];
    const float* WC = (const float*)d_in[11];
    const float* bC = (const float*)d_in[12];
    const float* gn_g = (const float*)d_in[13];
    const float* gn_b = (const float*)d_in[14];
    const float* ge_g = (const float*)d_in[15];
    const float* ge_b = (const float*)d_in[16];

    float* out   = (float*)d_out;
    float* out_x = out;
    float* out_e = out + (size_t)Nn * Dd;

    cudaFuncSetAttribute(node_mma_kernel, cudaFuncAttributeMaxDynamicSharedMemorySize, S_SIZE);
    cudaFuncSetAttribute(edge1_kernel, cudaFuncAttributeMaxDynamicSharedMemorySize, S_SIZE);

    detect_kernel<<<1, 256>>>((const unsigned*)ei);
    zero_kernel<<<2048, 256>>>();
    prep_w_kernel<<<5, 256>>>(Wu, Wv, WB, WC, WA);
    node_mma_kernel<<<dim3(74, 4), 256, S_SIZE>>>(x, bu, bv, bB, bC);
    edge1_kernel<<<296, 256, S_SIZE>>>(ea, ei, bA);
    finalize_kernel<<<1, 128>>>(0, 1.0f / (float)Ee);
    edge_pass2_kernel<<<(Ee + 7) / 8, 256>>>(ea, ei, ge_g, ge_b, out_e);
    node_stats_kernel<<<(Nn + 63) / 64, 128>>>();
    finalize_kernel<<<1, 128>>>(1, 1.0f / (float)Nn);
    node_out_kernel<<<(Nn * 32 + 255) / 256, 256>>>(x, gn_g, gn_b, out_x);
}

// round 8
// speedup vs baseline: 3.5634x; 1.3471x over previous
#include <cuda_runtime.h>
#include <cuda_bf16.h>
#include <cstdint>

#define Nn 50000
#define Ee 640000
#define Dd 128

#define ASTRIDE 136              // uint16 elems per row (128 + 8 pad)
#define ROWB    (ASTRIDE * 2)    // 272 bytes per row
#define WPLANE  (128 * ASTRIDE)  // uint16 elems per W plane
#define NT_E    (Ee / 32)        // 20000 edge tiles
#define NT_N    ((Nn + 31) / 32) // 1563 node tiles

// ---------------- device scratch ------------------------------------------
__device__ float g_U[Nn * 128];
__device__ float g_B[Nn * 128];
__device__ float g_CV[Nn * 256];                 // [Cx | Vx]
__device__ float g_edge_in[(size_t)Ee * 128];
__device__ float g_agg[Nn * 128];
__device__ float g_stats[1024];
__device__ __align__(16) uint16_t g_Wp[5 * 2 * WPLANE]; // pre-split W hi/lo planes
__device__ int g_is64;

// ---------------- smem layout (bytes) --------------------------------------
#define SB_BIAS 0                 // 512
#define SB_IDX  512               // 64 ints
#define SB_STAT 1024              // 256 floats
#define SB_F32  2048              // 2 x 16384 fp32 A staging (cp.async)
#define SB_BF16 34816             // hi 8704 + lo 8704
#define S_SIZE  52224
// W staging (one-time, prologue only) overlays SB_F32.. (34816 B needed)

// ---------------- PTX helpers ------------------------------------------------
__device__ __forceinline__ uint32_t smem_u32(const void* p) {
    uint32_t a;
    asm("{ .reg .u64 t; cvta.to.shared.u64 t, %1; cvt.u32.u64 %0, t; }" : "=r"(a) : "l"(p));
    return a;
}
__device__ __forceinline__ void ldsm4(uint32_t& r0, uint32_t& r1, uint32_t& r2,
                                      uint32_t& r3, uint32_t addr) {
    asm volatile("ldmatrix.sync.aligned.m8n8.x4.shared.b16 {%0,%1,%2,%3}, [%4];"
                 : "=r"(r0), "=r"(r1), "=r"(r2), "=r"(r3) : "r"(addr));
}
__device__ __forceinline__ void mma_bf16(float* d, uint32_t a0, uint32_t a1,
                                         uint32_t a2, uint32_t a3,
                                         uint32_t b0, uint32_t b1) {
    asm volatile("mma.sync.aligned.m16n8k16.row.col.f32.bf16.bf16.f32 "
        "{%0,%1,%2,%3}, {%4,%5,%6,%7}, {%8,%9}, {%0,%1,%2,%3};"
        : "+f"(d[0]), "+f"(d[1]), "+f"(d[2]), "+f"(d[3])
        : "r"(a0), "r"(a1), "r"(a2), "r"(a3), "r"(b0), "r"(b1));
}
__device__ __forceinline__ void cp_async16(uint32_t saddr, const void* gptr) {
    asm volatile("cp.async.cg.shared.global [%0], [%1], 16;" :: "r"(saddr), "l"(gptr));
}
#define CP_COMMIT() asm volatile("cp.async.commit_group;" ::: "memory")
#define CP_WAIT0()  asm volatile("cp.async.wait_group 0;" ::: "memory")

// stage a 32x128 fp32 tile via cp.async; OOB rows clamp to row 0 (guarded later)
__device__ __forceinline__ void cpa_tile(uint32_t sdst, const float* __restrict__ src,
                                         int valid_rows) {
#pragma unroll
    for (int p = 0; p < 4; p++) {
        int idx = p * 256 + threadIdx.x;
        int row = idx >> 5;
        const float4* g = (const float4*)src + (row < valid_rows ? idx : (idx & 31));
        cp_async16(sdst + idx * 16, g);
    }
}
// convert fp32 smem tile -> hi/lo bf16 planes in smem
__device__ __forceinline__ void cvt_smem(uint16_t* __restrict__ hi_dst,
                                         uint16_t* __restrict__ lo_dst,
                                         const float* __restrict__ srcf) {
#pragma unroll
    for (int p = 0; p < 4; p++) {
        int idx = p * 256 + threadIdx.x;
        int row = idx >> 5, k4 = (idx & 31) << 2;
        float4 v = ((const float4*)srcf)[idx];
        __nv_bfloat16 h0 = __float2bfloat16(v.x), h1 = __float2bfloat16(v.y);
        __nv_bfloat16 h2 = __float2bfloat16(v.z), h3 = __float2bfloat16(v.w);
        __nv_bfloat16 l0 = __float2bfloat16(v.x - __bfloat162float(h0));
        __nv_bfloat16 l1 = __float2bfloat16(v.y - __bfloat162float(h1));
        __nv_bfloat16 l2 = __float2bfloat16(v.z - __bfloat162float(h2));
        __nv_bfloat16 l3 = __float2bfloat16(v.w - __bfloat162float(h3));
        uint2 hi, lo;
        hi.x = ((uint32_t)__bfloat16_as_ushort(h1) << 16) | __bfloat16_as_ushort(h0);
        hi.y = ((uint32_t)__bfloat16_as_ushort(h3) << 16) | __bfloat16_as_ushort(h2);
        lo.x = ((uint32_t)__bfloat16_as_ushort(l1) << 16) | __bfloat16_as_ushort(l0);
        lo.y = ((uint32_t)__bfloat16_as_ushort(l3) << 16) | __bfloat16_as_ushort(l2);
        *(uint2*)(hi_dst + row * ASTRIDE + k4) = hi;
        *(uint2*)(lo_dst + row * ASTRIDE + k4) = lo;
    }
}
__device__ __forceinline__ int ld_idx(const void* p, size_t i, int is64) {
    return is64 ? (int)((const long long*)p)[i] : ((const int*)p)[i];
}

// stage W planes (one-time) and load this warp's B fragments into registers
__device__ __forceinline__ void load_breg(char* sm, uint32_t smb, int mtx,
                                          int wid, int lane,
                                          uint32_t bh[8][4], uint32_t bl[8][4]) {
    const int nb = wid * 16;
    const uint32_t woffs = smb + SB_F32
        + (uint32_t)(nb + (lane & 7) + ((lane >> 4) << 3)) * ROWB
        + (((lane >> 3) & 1) << 4);
    uint4* d = (uint4*)(sm + SB_F32);
    {
        const uint4* s = (const uint4*)(g_Wp + (size_t)mtx * 2 * WPLANE);
        for (int i = threadIdx.x; i < 2176; i += 256) d[i] = s[i];
        __syncthreads();
#pragma unroll
        for (int ks = 0; ks < 8; ks++)
            ldsm4(bh[ks][0], bh[ks][1], bh[ks][2], bh[ks][3], woffs + ks * 32);
        __syncthreads();
    }
    {
        const uint4* s = (const uint4*)(g_Wp + ((size_t)mtx * 2 + 1) * WPLANE);
        for (int i = threadIdx.x; i < 2176; i += 256) d[i] = s[i];
        __syncthreads();
#pragma unroll
        for (int ks = 0; ks < 8; ks++)
            ldsm4(bl[ks][0], bl[ks][1], bl[ks][2], bl[ks][3], woffs + ks * 32);
        __syncthreads();
    }
}

// 3-term MMA over a 32x128 tile with B cached in registers
__device__ __forceinline__ void mma_tile(uint32_t ah_base, uint32_t al_base,
                                         const uint32_t bh[8][4], const uint32_t bl[8][4],
                                         int lane, float acc[2][2][4]) {
#pragma unroll
    for (int mg = 0; mg < 2; mg++)
#pragma unroll
        for (int j = 0; j < 2; j++)
#pragma unroll
            for (int q = 0; q < 4; q++) acc[mg][j][q] = 0.f;
    const uint32_t aoff = (uint32_t)(lane & 15) * ROWB + ((lane >> 4) << 4);
#pragma unroll
    for (int ks = 0; ks < 8; ks++) {
#pragma unroll
        for (int mg = 0; mg < 2; mg++) {
            uint32_t a0, a1, a2, a3;
            ldsm4(a0, a1, a2, a3, ah_base + aoff + mg * 16 * ROWB + ks * 32);
            mma_bf16(acc[mg][0], a0, a1, a2, a3, bh[ks][0], bh[ks][1]);
            mma_bf16(acc[mg][1], a0, a1, a2, a3, bh[ks][2], bh[ks][3]);
            mma_bf16(acc[mg][0], a0, a1, a2, a3, bl[ks][0], bl[ks][1]);
            mma_bf16(acc[mg][1], a0, a1, a2, a3, bl[ks][2], bl[ks][3]);
            uint32_t c0, c1, c2, c3;
            ldsm4(c0, c1, c2, c3, al_base + aoff + mg * 16 * ROWB + ks * 32);
            mma_bf16(acc[mg][0], c0, c1, c2, c3, bh[ks][0], bh[ks][1]);
            mma_bf16(acc[mg][1], c0, c1, c2, c3, bh[ks][2], bh[ks][3]);
        }
    }
}

// ---------------- small kernels -----------------------------------------------
__global__ void detect_kernel(const unsigned* __restrict__ w) {
    __shared__ int sflag;
    if (threadIdx.x == 0) sflag = 0;
    __syncthreads();
    unsigned v = 0;
    for (int i = threadIdx.x; i < 2048; i += blockDim.x) v |= w[2 * i + 1];
    if (v) atomicOr(&sflag, 1);
    __syncthreads();
    if (threadIdx.x == 0) g_is64 = sflag ? 0 : 1;
}
__global__ void zero_kernel() {
    int i = blockIdx.x * blockDim.x + threadIdx.x;
    const int total = Nn * 128;
    for (int k = i; k < total; k += gridDim.x * blockDim.x) g_agg[k] = 0.f;
    if (i < 1024) g_stats[i] = 0.f;
}
__global__ void prep_w_kernel(const float* __restrict__ Wu, const float* __restrict__ Wv,
                              const float* __restrict__ WB, const float* __restrict__ WC,
                              const float* __restrict__ WA) {
    int mtx = blockIdx.x;
    const float* W = (mtx == 0) ? Wu : (mtx == 1) ? Wv : (mtx == 2) ? WB : (mtx == 3) ? WC : WA;
    uint16_t* hi = g_Wp + (size_t)mtx * 2 * WPLANE;
    uint16_t* lo = hi + WPLANE;
    for (int idx = threadIdx.x; idx < 16384; idx += blockDim.x) {
        int f = idx >> 7, k = idx & 127;
        float w = W[idx];
        __nv_bfloat16 h = __float2bfloat16(w);
        __nv_bfloat16 l = __float2bfloat16(w - __bfloat162float(h));
        hi[f * ASTRIDE + k] = __bfloat16_as_ushort(h);
        lo[f * ASTRIDE + k] = __bfloat16_as_ushort(l);
    }
}

// ---------------- node GEMMs: persistent, cp.async pipelined, B-in-regs ----------
__global__ void __launch_bounds__(256, 2) node_mma_kernel(
        const float* __restrict__ x, const float* __restrict__ bu,
        const float* __restrict__ bv, const float* __restrict__ bB,
        const float* __restrict__ bC) {
    extern __shared__ char sm[];
    uint32_t smb = smem_u32(sm);
    const int tid = threadIdx.x, wid = tid >> 5, lane = tid & 31;
    const int which = blockIdx.y;
    float* sb = (float*)(sm + SB_BIAS);
    const float* bias = (which == 0) ? bu : (which == 1) ? bv : (which == 2) ? bB : bC;
    if (tid < 128) sb[tid] = bias[tid];

    uint32_t bh[8][4], bl[8][4];
    load_breg(sm, smb, which, wid, lane, bh, bl);

    float* dst0;
    int rstride;
    if (which == 0)      { dst0 = g_U;        rstride = 128; }
    else if (which == 1) { dst0 = g_CV + 128; rstride = 256; }
    else if (which == 2) { dst0 = g_B;        rstride = 128; }
    else                 { dst0 = g_CV;       rstride = 256; }

    const int gid = lane >> 2, tig = lane & 3;
    const int nb = wid * 16;

    long t = blockIdx.x;
    if (t < NT_N) {
        int v0 = Nn - (int)t * 32; if (v0 > 32) v0 = 32;
        cpa_tile(smb + SB_F32, x + t * 4096, v0);
    }
    CP_COMMIT();
    int ib = 0;
    for (; t < NT_N; t += gridDim.x) {
        CP_WAIT0();
        __syncthreads();
        uint16_t* Ah = (uint16_t*)(sm + SB_BF16);
        cvt_smem(Ah, Ah + 4352, (const float*)(sm + SB_F32 + ib * 16384));
        long tn = t + gridDim.x;
        if (tn < NT_N) {
            int vn = Nn - (int)tn * 32; if (vn > 32) vn = 32;
            cpa_tile(smb + SB_F32 + (ib ^ 1) * 16384, x + tn * 4096, vn);
        }
        CP_COMMIT();
        __syncthreads();
        float acc[2][2][4];
        mma_tile(smb + SB_BF16, smb + SB_BF16 + 8704, bh, bl, lane, acc);
#pragma unroll
        for (int mg = 0; mg < 2; mg++) {
            const int r0 = (int)t * 32 + mg * 16 + gid;
#pragma unroll
            for (int j = 0; j < 2; j++) {
                int c = nb + j * 8 + tig * 2;
                float2 bb = *(const float2*)(sb + c);
                if (r0 < Nn)
                    *(float2*)(dst0 + (size_t)r0 * rstride + c) =
                        make_float2(acc[mg][j][0] + bb.x, acc[mg][j][1] + bb.y);
                if (r0 + 8 < Nn)
                    *(float2*)(dst0 + (size_t)(r0 + 8) * rstride + c) =
                        make_float2(acc[mg][j][2] + bb.x, acc[mg][j][3] + bb.y);
            }
        }
        ib ^= 1;
    }
}

// ---------------- edge pass 1 -------------------------------------------------------
__global__ void __launch_bounds__(256, 2) edge1_kernel(
        const float* __restrict__ ea, const void* __restrict__ eidx,
        const float* __restrict__ bA) {
    extern __shared__ char sm[];
    uint32_t smb = smem_u32(sm);
    const int tid = threadIdx.x, wid = tid >> 5, lane = tid & 31;
    const int is64 = g_is64;
    float* sb = (float*)(sm + SB_BIAS);
    int* sidx = (int*)(sm + SB_IDX);
    float* sstat = (float*)(sm + SB_STAT);
    if (tid < 128) sb[tid] = bA[tid];
    sstat[tid] = 0.f;

    uint32_t bh[8][4], bl[8][4];
    load_breg(sm, smb, 4, wid, lane, bh, bl);

    const int gid = lane >> 2, tig = lane & 3;
    const int nb = wid * 16;

    long t = blockIdx.x;
    int idxreg = 0;
    if (t < NT_E) {
        cpa_tile(smb + SB_F32, ea + t * 4096, 32);
        if (tid < 64)
            idxreg = ld_idx(eidx, (tid < 32) ? (t * 32 + tid)
                                             : ((size_t)Ee + t * 32 + (tid - 32)), is64);
    }
    CP_COMMIT();
    int ib = 0;
    for (; t < NT_E; t += gridDim.x) {
        CP_WAIT0();
        __syncthreads();
        if (tid < 64) sidx[tid] = idxreg;
        uint16_t* Ah = (uint16_t*)(sm + SB_BF16);
        cvt_smem(Ah, Ah + 4352, (const float*)(sm + SB_F32 + ib * 16384));
        long tn = t + gridDim.x;
        if (tn < NT_E) {
            cpa_tile(smb + SB_F32 + (ib ^ 1) * 16384, ea + tn * 4096, 32);
            if (tid < 64)
                idxreg = ld_idx(eidx, (tid < 32) ? (tn * 32 + tid)
                                                 : ((size_t)Ee + tn * 32 + (tid - 32)), is64);
        }
        CP_COMMIT();
        __syncthreads();
        float acc[2][2][4];
        mma_tile(smb + SB_BF16, smb + SB_BF16 + 8704, bh, bl, lane, acc);

        // 4 rows owned by this thread: gid, gid+8, 16+gid, 24+gid
        const int r00 = gid, r01 = gid + 8, r10 = 16 + gid, r11 = 24 + gid;
        const int ri00 = sidx[r00], ci00 = sidx[32 + r00];
        const int ri01 = sidx[r01], ci01 = sidx[32 + r01];
        const int ri10 = sidx[r10], ci10 = sidx[32 + r10];
        const int ri11 = sidx[r11], ci11 = sidx[32 + r11];
#pragma unroll
        for (int j = 0; j < 2; j++) {
            int c = nb + j * 8 + tig * 2;
            float2 ba = *(const float2*)(sb + c);
            float2 B00 = *(const float2*)(g_B + (size_t)ri00 * 128 + c);
            float2 C00 = *(const float2*)(g_CV + (size_t)ci00 * 256 + c);
            float2 B01 = *(const float2*)(g_B + (size_t)ri01 * 128 + c);
            float2 C01 = *(const float2*)(g_CV + (size_t)ci01 * 256 + c);
            float2 B10 = *(const float2*)(g_B + (size_t)ri10 * 128 + c);
            float2 C10 = *(const float2*)(g_CV + (size_t)ci10 * 256 + c);
            float2 B11 = *(const float2*)(g_B + (size_t)ri11 * 128 + c);
            float2 C11 = *(const float2*)(g_CV + (size_t)ci11 * 256 + c);
            float v00x = acc[0][j][0] + ba.x + B00.x + C00.x;
            float v00y = acc[0][j][1] + ba.y + B00.y + C00.y;
            float v01x = acc[0][j][2] + ba.x + B01.x + C01.x;
            float v01y = acc[0][j][3] + ba.y + B01.y + C01.y;
            float v10x = acc[1][j][0] + ba.x + B10.x + C10.x;
            float v10y = acc[1][j][1] + ba.y + B10.y + C10.y;
            float v11x = acc[1][j][2] + ba.x + B11.x + C11.x;
            float v11y = acc[1][j][3] + ba.y + B11.y + C11.y;
            *(float2*)(g_edge_in + (t * 32 + r00) * 128 + c) = make_float2(v00x, v00y);
            *(float2*)(g_edge_in + (t * 32 + r01) * 128 + c) = make_float2(v01x, v01y);
            *(float2*)(g_edge_in + (t * 32 + r10) * 128 + c) = make_float2(v10x, v10y);
            *(float2*)(g_edge_in + (t * 32 + r11) * 128 + c) = make_float2(v11x, v11y);
            float p1 = v00x + v01x + v10x + v11x;
            float p2 = v00y + v01y + v10y + v11y;
            float q1 = v00x * v00x + v01x * v01x + v10x * v10x + v11x * v11x;
            float q2 = v00y * v00y + v01y * v01y + v10y * v10y + v11y * v11y;
#pragma unroll
            for (int o = 4; o < 32; o <<= 1) {
                p1 += __shfl_xor_sync(0xFFFFFFFFu, p1, o);
                p2 += __shfl_xor_sync(0xFFFFFFFFu, p2, o);
                q1 += __shfl_xor_sync(0xFFFFFFFFu, q1, o);
                q2 += __shfl_xor_sync(0xFFFFFFFFu, q2, o);
            }
            if (gid == 0) {
                atomicAdd(&sstat[c], p1);
                atomicAdd(&sstat[c + 1], p2);
                atomicAdd(&sstat[128 + c], q1);
                atomicAdd(&sstat[128 + c + 1], q2);
            }
        }
        ib ^= 1;
    }
    __syncthreads();
    atomicAdd(&g_stats[tid], sstat[tid]);
}

// ---------------- finalize BN stats (0=edge, 1=node) --------------------------------
__global__ void finalize_kernel(int which, float inv) {
    int f = threadIdx.x;
    float s1 = g_stats[which * 256 + f];
    float s2 = g_stats[which * 256 + 128 + f];
    float mean = s1 * inv;
    float var = fmaxf(s2 * inv - mean * mean, 0.f);
    g_stats[512 + which * 256 + f] = mean;
    g_stats[512 + which * 256 + 128 + f] = rsqrtf(var + 1e-5f);
}

// ---------------- edge pass 2 ----------------------------------------------------------
__global__ void edge_pass2_kernel(const float* __restrict__ ea, const void* __restrict__ eidx,
                                  const float* __restrict__ gam, const float* __restrict__ bet,
                                  float* __restrict__ out_e) {
    int e = blockIdx.x * 8 + (threadIdx.x >> 5);
    if (e >= Ee) return;
    int c = (threadIdx.x & 31) * 4;
    int row, col;
    if (g_is64) {
        const long long* p = (const long long*)eidx;
        row = (int)p[e];
        col = (int)p[(size_t)Ee + e];
    } else {
        const int* p = (const int*)eidx;
        row = p[e];
        col = p[Ee + e];
    }
    size_t base = (size_t)e * 128 + c;
    float4 ein = *(const float4*)(g_edge_in + base);
    float4 mu = *(const float4*)(g_stats + 512 + c);
    float4 rs = *(const float4*)(g_stats + 640 + c);
    float4 gm = __ldg((const float4*)(gam + c));
    float4 bt = __ldg((const float4*)(bet + c));
    float4 a4 = __ldg((const float4*)(ea + base));
    float4 eo;
    eo.x = a4.x + fmaxf(gm.x * (ein.x - mu.x) * rs.x + bt.x, 0.f);
    eo.y = a4.y + fmaxf(gm.y * (ein.y - mu.y) * rs.y + bt.y, 0.f);
    eo.z = a4.z + fmaxf(gm.z * (ein.z - mu.z) * rs.z + bt.z, 0.f);
    eo.w = a4.w + fmaxf(gm.w * (ein.w - mu.w) * rs.w + bt.w, 0.f);
    *(float4*)(out_e + base) = eo;

    float4 v4 = *(const float4*)(g_CV + (size_t)col * 256 + 128 + c);
    float mx = v4.x / (1.f + __expf(-eo.x));
    float my = v4.y / (1.f + __expf(-eo.y));
    float mz = v4.z / (1.f + __expf(-eo.z));
    float mw = v4.w / (1.f + __expf(-eo.w));
    float* dst = g_agg + (size_t)row * 128 + c;
    asm volatile("red.global.add.v4.f32 [%0], {%1, %2, %3, %4};"
                 :: "l"(dst), "f"(mx), "f"(my), "f"(mz), "f"(mw) : "memory");
}

// ---------------- node stats / output ---------------------------------------------------
__global__ void node_stats_kernel() {
    int f = threadIdx.x;
    int n0 = blockIdx.x * 64;
    float s1 = 0.f, s2 = 0.f;
    for (int r = 0; r < 64; r++) {
        int n = n0 + r;
        if (n < Nn) {
            float v = g_U[(size_t)n * 128 + f] + g_agg[(size_t)n * 128 + f];
            s1 += v;
            s2 += v * v;
        }
    }
    atomicAdd(&g_stats[256 + f], s1);
    atomicAdd(&g_stats[384 + f], s2);
}
__global__ void node_out_kernel(const float* __restrict__ x, const float* __restrict__ gam,
                                const float* __restrict__ bet, float* __restrict__ out_x) {
    int i = blockIdx.x * blockDim.x + threadIdx.x;
    if (i >= Nn * 32) return;
    int c = (i & 31) * 4;
    size_t base = (size_t)i * 4;
    float4 u = *(const float4*)(g_U + base);
    float4 a = *(const float4*)(g_agg + base);
    float4 mu = *(const float4*)(g_stats + 768 + c);
    float4 rs = *(const float4*)(g_stats + 896 + c);
    float4 gm = __ldg((const float4*)(gam + c));
    float4 bt = __ldg((const float4*)(bet + c));
    float4 xv = __ldg((const float4*)(x + base));
    float4 o;
    o.x = xv.x + fmaxf(gm.x * ((u.x + a.x) - mu.x) * rs.x + bt.x, 0.f);
    o.y = xv.y + fmaxf(gm.y * ((u.y + a.y) - mu.y) * rs.y + bt.y, 0.f);
    o.z = xv.z + fmaxf(gm.z * ((u.z + a.z) - mu.z) * rs.z + bt.z, 0.f);
    o.w = xv.w + fmaxf(gm.w * ((u.w + a.w) - mu.w) * rs.w + bt.w, 0.f);
    *(float4*)(out_x + base) = o;
}

// ---------------- launch -----------------------------------------------------------------
extern "C" void kernel_launch(void* const* d_in, const int* in_sizes, int n_in,
                              void* d_out, int out_size) {
    (void)in_sizes; (void)n_in; (void)out_size;
    const float* x  = (const float*)d_in[0];
    const void*  ei = d_in[1];
    const float* ea = (const float*)d_in[2];
    const float* Wu = (const float*)d_in[3];
    const float* bu = (const float*)d_in[4];
    const float* Wv = (const float*)d_in[5];
    const float* bv = (const float*)d_in[6];
    const float* WA = (const float*)d_in[7];
    const float* bA = (const float*)d_in[8];
    const float* WB = (const float*)d_in[9];
    const float* bB = (const float*)d_in[10];
    const float* WC = (const float*)d_in[11];
    const float* bC = (const float*)d_in[12];
    const float* gn_g = (const float*)d_in[13];
    const float* gn_b = (const float*)d_in[14];
    const float* ge_g = (const float*)d_in[15];
    const float* ge_b = (const float*)d_in[16];

    float* out   = (float*)d_out;
    float* out_x = out;
    float* out_e = out + (size_t)Nn * Dd;

    cudaFuncSetAttribute(node_mma_kernel, cudaFuncAttributeMaxDynamicSharedMemorySize, S_SIZE);
    cudaFuncSetAttribute(edge1_kernel, cudaFuncAttributeMaxDynamicSharedMemorySize, S_SIZE);

    detect_kernel<<<1, 256>>>((const unsigned*)ei);
    zero_kernel<<<2048, 256>>>();
    prep_w_kernel<<<5, 256>>>(Wu, Wv, WB, WC, WA);
    node_mma_kernel<<<dim3(74, 4), 256, S_SIZE>>>(x, bu, bv, bB, bC);
    edge1_kernel<<<296, 256, S_SIZE>>>(ea, ei, bA);
    finalize_kernel<<<1, 128>>>(0, 1.0f / (float)Ee);
    edge_pass2_kernel<<<(Ee + 7) / 8, 256>>>(ea, ei, ge_g, ge_b, out_e);
    node_stats_kernel<<<(Nn + 63) / 64, 128>>>();
    finalize_kernel<<<1, 128>>>(1, 1.0f / (float)Nn);
    node_out_kernel<<<(Nn * 32 + 255) / 256, 256>>>(x, gn_g, gn_b, out_x);
}

// round 9
// speedup vs baseline: 3.6586x; 1.0267x over previous
#include <cuda_runtime.h>
#include <cuda_bf16.h>
#include <cstdint>

#define Nn 50000
#define Ee 640000
#define Dd 128

#define ASTRIDE 136              // uint16 elems per row (128 + 8 pad)
#define ROWB    (ASTRIDE * 2)    // 272 bytes per row
#define WPLANE  (128 * ASTRIDE)  // uint16 elems per W plane
#define NT_E    (Ee / 32)        // 20000 edge tiles
#define NT_N    ((Nn + 31) / 32) // 1563 node tiles

// ---------------- device scratch ------------------------------------------
__device__ float g_U[Nn * 128];
__device__ float g_B[Nn * 128];
__device__ float g_CV[Nn * 256];                 // [Cx | Vx]
__device__ float g_edge_in[(size_t)Ee * 128];
__device__ float g_agg[Nn * 128];
__device__ float g_stats[1024];
__device__ __align__(16) uint16_t g_Wp[5 * 2 * WPLANE]; // pre-split W hi/lo planes
__device__ int g_is64;

// ---------------- smem layout (bytes) --------------------------------------
#define SB_BIAS 0                 // 512
#define SB_IDX  512               // 64 ints
#define SB_F32  2048              // 2 x 16384 fp32 A staging (cp.async)
#define SB_BF16 34816             // hi 8704 + lo 8704
#define SB_ACC  52224             // 32 x 132 fp32 = 16896
#define S_SIZE_N 52224            // node kernel
#define S_SIZE_E 69120            // edge kernel (includes ACC)

// ---------------- PTX helpers ------------------------------------------------
__device__ __forceinline__ uint32_t smem_u32(const void* p) {
    uint32_t a;
    asm("{ .reg .u64 t; cvta.to.shared.u64 t, %1; cvt.u32.u64 %0, t; }" : "=r"(a) : "l"(p));
    return a;
}
__device__ __forceinline__ void ldsm4(uint32_t& r0, uint32_t& r1, uint32_t& r2,
                                      uint32_t& r3, uint32_t addr) {
    asm volatile("ldmatrix.sync.aligned.m8n8.x4.shared.b16 {%0,%1,%2,%3}, [%4];"
                 : "=r"(r0), "=r"(r1), "=r"(r2), "=r"(r3) : "r"(addr));
}
__device__ __forceinline__ void mma_bf16(float* d, uint32_t a0, uint32_t a1,
                                         uint32_t a2, uint32_t a3,
                                         uint32_t b0, uint32_t b1) {
    asm volatile("mma.sync.aligned.m16n8k16.row.col.f32.bf16.bf16.f32 "
        "{%0,%1,%2,%3}, {%4,%5,%6,%7}, {%8,%9}, {%0,%1,%2,%3};"
        : "+f"(d[0]), "+f"(d[1]), "+f"(d[2]), "+f"(d[3])
        : "r"(a0), "r"(a1), "r"(a2), "r"(a3), "r"(b0), "r"(b1));
}
__device__ __forceinline__ void cp_async16(uint32_t saddr, const void* gptr) {
    asm volatile("cp.async.cg.shared.global [%0], [%1], 16;" :: "r"(saddr), "l"(gptr));
}
#define CP_COMMIT() asm volatile("cp.async.commit_group;" ::: "memory")
#define CP_WAIT0()  asm volatile("cp.async.wait_group 0;" ::: "memory")

// stage a 32x128 fp32 tile via cp.async; OOB rows clamp to row 0 (guarded later)
__device__ __forceinline__ void cpa_tile(uint32_t sdst, const float* __restrict__ src,
                                         int valid_rows) {
#pragma unroll
    for (int p = 0; p < 4; p++) {
        int idx = p * 256 + threadIdx.x;
        int row = idx >> 5;
        const float4* g = (const float4*)src + (row < valid_rows ? idx : (idx & 31));
        cp_async16(sdst + idx * 16, g);
    }
}
// convert fp32 smem tile -> hi/lo bf16 planes in smem
__device__ __forceinline__ void cvt_smem(uint16_t* __restrict__ hi_dst,
                                         uint16_t* __restrict__ lo_dst,
                                         const float* __restrict__ srcf) {
#pragma unroll
    for (int p = 0; p < 4; p++) {
        int idx = p * 256 + threadIdx.x;
        int row = idx >> 5, k4 = (idx & 31) << 2;
        float4 v = ((const float4*)srcf)[idx];
        __nv_bfloat16 h0 = __float2bfloat16(v.x), h1 = __float2bfloat16(v.y);
        __nv_bfloat16 h2 = __float2bfloat16(v.z), h3 = __float2bfloat16(v.w);
        __nv_bfloat16 l0 = __float2bfloat16(v.x - __bfloat162float(h0));
        __nv_bfloat16 l1 = __float2bfloat16(v.y - __bfloat162float(h1));
        __nv_bfloat16 l2 = __float2bfloat16(v.z - __bfloat162float(h2));
        __nv_bfloat16 l3 = __float2bfloat16(v.w - __bfloat162float(h3));
        uint2 hi, lo;
        hi.x = ((uint32_t)__bfloat16_as_ushort(h1) << 16) | __bfloat16_as_ushort(h0);
        hi.y = ((uint32_t)__bfloat16_as_ushort(h3) << 16) | __bfloat16_as_ushort(h2);
        lo.x = ((uint32_t)__bfloat16_as_ushort(l1) << 16) | __bfloat16_as_ushort(l0);
        lo.y = ((uint32_t)__bfloat16_as_ushort(l3) << 16) | __bfloat16_as_ushort(l2);
        *(uint2*)(hi_dst + row * ASTRIDE + k4) = hi;
        *(uint2*)(lo_dst + row * ASTRIDE + k4) = lo;
    }
}
__device__ __forceinline__ int ld_idx(const void* p, size_t i, int is64) {
    return is64 ? (int)((const long long*)p)[i] : ((const int*)p)[i];
}

// stage W planes (one-time) and load this warp's B fragments into registers
__device__ __forceinline__ void load_breg(char* sm, uint32_t smb, int mtx,
                                          int wid, int lane,
                                          uint32_t bh[8][4], uint32_t bl[8][4]) {
    const int nb = wid * 16;
    const uint32_t woffs = smb + SB_F32
        + (uint32_t)(nb + (lane & 7) + ((lane >> 4) << 3)) * ROWB
        + (((lane >> 3) & 1) << 4);
    uint4* d = (uint4*)(sm + SB_F32);
    {
        const uint4* s = (const uint4*)(g_Wp + (size_t)mtx * 2 * WPLANE);
        for (int i = threadIdx.x; i < 2176; i += 256) d[i] = s[i];
        __syncthreads();
#pragma unroll
        for (int ks = 0; ks < 8; ks++)
            ldsm4(bh[ks][0], bh[ks][1], bh[ks][2], bh[ks][3], woffs + ks * 32);
        __syncthreads();
    }
    {
        const uint4* s = (const uint4*)(g_Wp + ((size_t)mtx * 2 + 1) * WPLANE);
        for (int i = threadIdx.x; i < 2176; i += 256) d[i] = s[i];
        __syncthreads();
#pragma unroll
        for (int ks = 0; ks < 8; ks++)
            ldsm4(bl[ks][0], bl[ks][1], bl[ks][2], bl[ks][3], woffs + ks * 32);
        __syncthreads();
    }
}

// 3-term MMA over a 32x128 tile with B cached in registers
__device__ __forceinline__ void mma_tile(uint32_t ah_base, uint32_t al_base,
                                         const uint32_t bh[8][4], const uint32_t bl[8][4],
                                         int lane, float acc[2][2][4]) {
#pragma unroll
    for (int mg = 0; mg < 2; mg++)
#pragma unroll
        for (int j = 0; j < 2; j++)
#pragma unroll
            for (int q = 0; q < 4; q++) acc[mg][j][q] = 0.f;
    const uint32_t aoff = (uint32_t)(lane & 15) * ROWB + ((lane >> 4) << 4);
#pragma unroll
    for (int ks = 0; ks < 8; ks++) {
#pragma unroll
        for (int mg = 0; mg < 2; mg++) {
            uint32_t a0, a1, a2, a3;
            ldsm4(a0, a1, a2, a3, ah_base + aoff + mg * 16 * ROWB + ks * 32);
            mma_bf16(acc[mg][0], a0, a1, a2, a3, bh[ks][0], bh[ks][1]);
            mma_bf16(acc[mg][1], a0, a1, a2, a3, bh[ks][2], bh[ks][3]);
            mma_bf16(acc[mg][0], a0, a1, a2, a3, bl[ks][0], bl[ks][1]);
            mma_bf16(acc[mg][1], a0, a1, a2, a3, bl[ks][2], bl[ks][3]);
            uint32_t c0, c1, c2, c3;
            ldsm4(c0, c1, c2, c3, al_base + aoff + mg * 16 * ROWB + ks * 32);
            mma_bf16(acc[mg][0], c0, c1, c2, c3, bh[ks][0], bh[ks][1]);
            mma_bf16(acc[mg][1], c0, c1, c2, c3, bh[ks][2], bh[ks][3]);
        }
    }
}

// ---------------- small kernels -----------------------------------------------
__global__ void detect_kernel(const unsigned* __restrict__ w) {
    __shared__ int sflag;
    if (threadIdx.x == 0) sflag = 0;
    __syncthreads();
    unsigned v = 0;
    for (int i = threadIdx.x; i < 2048; i += blockDim.x) v |= w[2 * i + 1];
    if (v) atomicOr(&sflag, 1);
    __syncthreads();
    if (threadIdx.x == 0) g_is64 = sflag ? 0 : 1;
}
__global__ void zero_kernel() {
    int i = blockIdx.x * blockDim.x + threadIdx.x;
    const int total = Nn * 128;
    for (int k = i; k < total; k += gridDim.x * blockDim.x) g_agg[k] = 0.f;
    if (i < 1024) g_stats[i] = 0.f;
}
__global__ void prep_w_kernel(const float* __restrict__ Wu, const float* __restrict__ Wv,
                              const float* __restrict__ WB, const float* __restrict__ WC,
                              const float* __restrict__ WA) {
    int mtx = blockIdx.x;
    const float* W = (mtx == 0) ? Wu : (mtx == 1) ? Wv : (mtx == 2) ? WB : (mtx == 3) ? WC : WA;
    uint16_t* hi = g_Wp + (size_t)mtx * 2 * WPLANE;
    uint16_t* lo = hi + WPLANE;
    for (int idx = threadIdx.x; idx < 16384; idx += blockDim.x) {
        int f = idx >> 7, k = idx & 127;
        float w = W[idx];
        __nv_bfloat16 h = __float2bfloat16(w);
        __nv_bfloat16 l = __float2bfloat16(w - __bfloat162float(h));
        hi[f * ASTRIDE + k] = __bfloat16_as_ushort(h);
        lo[f * ASTRIDE + k] = __bfloat16_as_ushort(l);
    }
}

// ---------------- node GEMMs: persistent, cp.async pipelined, B-in-regs ----------
__global__ void __launch_bounds__(256, 2) node_mma_kernel(
        const float* __restrict__ x, const float* __restrict__ bu,
        const float* __restrict__ bv, const float* __restrict__ bB,
        const float* __restrict__ bC) {
    extern __shared__ char sm[];
    uint32_t smb = smem_u32(sm);
    const int tid = threadIdx.x, wid = tid >> 5, lane = tid & 31;
    const int which = blockIdx.y;
    float* sb = (float*)(sm + SB_BIAS);
    const float* bias = (which == 0) ? bu : (which == 1) ? bv : (which == 2) ? bB : bC;
    if (tid < 128) sb[tid] = bias[tid];

    uint32_t bh[8][4], bl[8][4];
    load_breg(sm, smb, which, wid, lane, bh, bl);

    float* dst0;
    int rstride;
    if (which == 0)      { dst0 = g_U;        rstride = 128; }
    else if (which == 1) { dst0 = g_CV + 128; rstride = 256; }
    else if (which == 2) { dst0 = g_B;        rstride = 128; }
    else                 { dst0 = g_CV;       rstride = 256; }

    const int gid = lane >> 2, tig = lane & 3;
    const int nb = wid * 16;

    long t = blockIdx.x;
    if (t < NT_N) {
        int v0 = Nn - (int)t * 32; if (v0 > 32) v0 = 32;
        cpa_tile(smb + SB_F32, x + t * 4096, v0);
    }
    CP_COMMIT();
    int ib = 0;
    for (; t < NT_N; t += gridDim.x) {
        CP_WAIT0();
        __syncthreads();
        uint16_t* Ah = (uint16_t*)(sm + SB_BF16);
        cvt_smem(Ah, Ah + 4352, (const float*)(sm + SB_F32 + ib * 16384));
        long tn = t + gridDim.x;
        if (tn < NT_N) {
            int vn = Nn - (int)tn * 32; if (vn > 32) vn = 32;
            cpa_tile(smb + SB_F32 + (ib ^ 1) * 16384, x + tn * 4096, vn);
        }
        CP_COMMIT();
        __syncthreads();
        float acc[2][2][4];
        mma_tile(smb + SB_BF16, smb + SB_BF16 + 8704, bh, bl, lane, acc);
#pragma unroll
        for (int mg = 0; mg < 2; mg++) {
            const int r0 = (int)t * 32 + mg * 16 + gid;
#pragma unroll
            for (int j = 0; j < 2; j++) {
                int c = nb + j * 8 + tig * 2;
                float2 bb = *(const float2*)(sb + c);
                if (r0 < Nn)
                    *(float2*)(dst0 + (size_t)r0 * rstride + c) =
                        make_float2(acc[mg][j][0] + bb.x, acc[mg][j][1] + bb.y);
                if (r0 + 8 < Nn)
                    *(float2*)(dst0 + (size_t)(r0 + 8) * rstride + c) =
                        make_float2(acc[mg][j][2] + bb.x, acc[mg][j][3] + bb.y);
            }
        }
        ib ^= 1;
    }
}

// ---------------- edge pass 1: coalesced epilogue via smem roundtrip ---------------
__global__ void __launch_bounds__(256, 2) edge1_kernel(
        const float* __restrict__ ea, const void* __restrict__ eidx,
        const float* __restrict__ bA) {
    extern __shared__ char sm[];
    uint32_t smb = smem_u32(sm);
    const int tid = threadIdx.x, wid = tid >> 5, lane = tid & 31;
    const int is64 = g_is64;
    float* sb = (float*)(sm + SB_BIAS);
    int* sidx = (int*)(sm + SB_IDX);
    float* sacc = (float*)(sm + SB_ACC);
    if (tid < 128) sb[tid] = bA[tid];

    uint32_t bh[8][4], bl[8][4];
    load_breg(sm, smb, 4, wid, lane, bh, bl);   // has syncthreads inside

    const int gid = lane >> 2, tig = lane & 3;
    const int nb = wid * 16;
    const float4 bias4 = *(const float4*)(sb + lane * 4);
    float s1[4] = {0.f, 0.f, 0.f, 0.f};
    float s2[4] = {0.f, 0.f, 0.f, 0.f};

    long t = blockIdx.x;
    int idxreg = 0;
    if (t < NT_E) {
        cpa_tile(smb + SB_F32, ea + t * 4096, 32);
        if (tid < 64)
            idxreg = ld_idx(eidx, (tid < 32) ? (t * 32 + tid)
                                             : ((size_t)Ee + t * 32 + (tid - 32)), is64);
    }
    CP_COMMIT();
    int ib = 0;
    for (; t < NT_E; t += gridDim.x) {
        CP_WAIT0();
        __syncthreads();
        if (tid < 64) sidx[tid] = idxreg;
        uint16_t* Ah = (uint16_t*)(sm + SB_BF16);
        cvt_smem(Ah, Ah + 4352, (const float*)(sm + SB_F32 + ib * 16384));
        long tn = t + gridDim.x;
        if (tn < NT_E) {
            cpa_tile(smb + SB_F32 + (ib ^ 1) * 16384, ea + tn * 4096, 32);
            if (tid < 64)
                idxreg = ld_idx(eidx, (tid < 32) ? (tn * 32 + tid)
                                                 : ((size_t)Ee + tn * 32 + (tid - 32)), is64);
        }
        CP_COMMIT();
        __syncthreads();
        float acc[2][2][4];
        mma_tile(smb + SB_BF16, smb + SB_BF16 + 8704, bh, bl, lane, acc);

        // dump accumulators to smem (32 x 132 fp32)
#pragma unroll
        for (int mg = 0; mg < 2; mg++) {
            int r = mg * 16 + gid;
#pragma unroll
            for (int j = 0; j < 2; j++) {
                int c = nb + j * 8 + tig * 2;
                *(float2*)(sacc + r * 132 + c) = make_float2(acc[mg][j][0], acc[mg][j][1]);
                *(float2*)(sacc + (r + 8) * 132 + c) = make_float2(acc[mg][j][2], acc[mg][j][3]);
            }
        }
        __syncthreads();

        // warp wid handles edges wid*4 .. wid*4+3 with fully coalesced rows
#pragma unroll
        for (int k = 0; k < 4; k++) {
            int r = wid * 4 + k;
            int ridx = sidx[r], cidx = sidx[32 + r];
            float4 a = *(const float4*)(sacc + r * 132 + lane * 4);
            float4 b = *(const float4*)(g_B + (size_t)ridx * 128 + lane * 4);
            float4 cg = *(const float4*)(g_CV + (size_t)cidx * 256 + lane * 4);
            float4 v;
            v.x = a.x + bias4.x + b.x + cg.x;
            v.y = a.y + bias4.y + b.y + cg.y;
            v.z = a.z + bias4.z + b.z + cg.z;
            v.w = a.w + bias4.w + b.w + cg.w;
            *(float4*)(g_edge_in + (t * 32 + r) * 128 + lane * 4) = v;
            s1[0] += v.x; s2[0] = fmaf(v.x, v.x, s2[0]);
            s1[1] += v.y; s2[1] = fmaf(v.y, v.y, s2[1]);
            s1[2] += v.z; s2[2] = fmaf(v.z, v.z, s2[2]);
            s1[3] += v.w; s2[3] = fmaf(v.w, v.w, s2[3]);
        }
        ib ^= 1;
    }
    // block-level stat reduction: sacc reused as scratch (2048 floats)
    __syncthreads();
#pragma unroll
    for (int q = 0; q < 4; q++) {
        sacc[wid * 128 + lane * 4 + q] = s1[q];
        sacc[1024 + wid * 128 + lane * 4 + q] = s2[q];
    }
    __syncthreads();
    if (tid < 128) {
        float a = 0.f, b = 0.f;
#pragma unroll
        for (int w = 0; w < 8; w++) {
            a += sacc[w * 128 + tid];
            b += sacc[1024 + w * 128 + tid];
        }
        atomicAdd(&g_stats[tid], a);
        atomicAdd(&g_stats[128 + tid], b);
    }
}

// ---------------- finalize BN stats (0=edge, 1=node) --------------------------------
__global__ void finalize_kernel(int which, float inv) {
    int f = threadIdx.x;
    float s1 = g_stats[which * 256 + f];
    float s2 = g_stats[which * 256 + 128 + f];
    float mean = s1 * inv;
    float var = fmaxf(s2 * inv - mean * mean, 0.f);
    g_stats[512 + which * 256 + f] = mean;
    g_stats[512 + which * 256 + 128 + f] = rsqrtf(var + 1e-5f);
}

// ---------------- edge pass 2 ----------------------------------------------------------
__global__ void edge_pass2_kernel(const float* __restrict__ ea, const void* __restrict__ eidx,
                                  const float* __restrict__ gam, const float* __restrict__ bet,
                                  float* __restrict__ out_e) {
    int e = blockIdx.x * 8 + (threadIdx.x >> 5);
    if (e >= Ee) return;
    int c = (threadIdx.x & 31) * 4;
    int row, col;
    if (g_is64) {
        const long long* p = (const long long*)eidx;
        row = (int)p[e];
        col = (int)p[(size_t)Ee + e];
    } else {
        const int* p = (const int*)eidx;
        row = p[e];
        col = p[Ee + e];
    }
    size_t base = (size_t)e * 128 + c;
    float4 ein = *(const float4*)(g_edge_in + base);
    float4 mu = *(const float4*)(g_stats + 512 + c);
    float4 rs = *(const float4*)(g_stats + 640 + c);
    float4 gm = __ldg((const float4*)(gam + c));
    float4 bt = __ldg((const float4*)(bet + c));
    float4 a4 = __ldg((const float4*)(ea + base));
    float4 eo;
    eo.x = a4.x + fmaxf(gm.x * (ein.x - mu.x) * rs.x + bt.x, 0.f);
    eo.y = a4.y + fmaxf(gm.y * (ein.y - mu.y) * rs.y + bt.y, 0.f);
    eo.z = a4.z + fmaxf(gm.z * (ein.z - mu.z) * rs.z + bt.z, 0.f);
    eo.w = a4.w + fmaxf(gm.w * (ein.w - mu.w) * rs.w + bt.w, 0.f);
    *(float4*)(out_e + base) = eo;

    float4 v4 = *(const float4*)(g_CV + (size_t)col * 256 + 128 + c);
    float mx = v4.x / (1.f + __expf(-eo.x));
    float my = v4.y / (1.f + __expf(-eo.y));
    float mz = v4.z / (1.f + __expf(-eo.z));
    float mw = v4.w / (1.f + __expf(-eo.w));
    float* dst = g_agg + (size_t)row * 128 + c;
    asm volatile("red.global.add.v4.f32 [%0], {%1, %2, %3, %4};"
                 :: "l"(dst), "f"(mx), "f"(my), "f"(mz), "f"(mw) : "memory");
}

// ---------------- node stats / output ---------------------------------------------------
__global__ void node_stats_kernel() {
    int f = threadIdx.x;
    int n0 = blockIdx.x * 64;
    float s1 = 0.f, s2 = 0.f;
    for (int r = 0; r < 64; r++) {
        int n = n0 + r;
        if (n < Nn) {
            float v = g_U[(size_t)n * 128 + f] + g_agg[(size_t)n * 128 + f];
            s1 += v;
            s2 += v * v;
        }
    }
    atomicAdd(&g_stats[256 + f], s1);
    atomicAdd(&g_stats[384 + f], s2);
}
__global__ void node_out_kernel(const float* __restrict__ x, const float* __restrict__ gam,
                                const float* __restrict__ bet, float* __restrict__ out_x) {
    int i = blockIdx.x * blockDim.x + threadIdx.x;
    if (i >= Nn * 32) return;
    int c = (i & 31) * 4;
    size_t base = (size_t)i * 4;
    float4 u = *(const float4*)(g_U + base);
    float4 a = *(const float4*)(g_agg + base);
    float4 mu = *(const float4*)(g_stats + 768 + c);
    float4 rs = *(const float4*)(g_stats + 896 + c);
    float4 gm = __ldg((const float4*)(gam + c));
    float4 bt = __ldg((const float4*)(bet + c));
    float4 xv = __ldg((const float4*)(x + base));
    float4 o;
    o.x = xv.x + fmaxf(gm.x * ((u.x + a.x) - mu.x) * rs.x + bt.x, 0.f);
    o.y = xv.y + fmaxf(gm.y * ((u.y + a.y) - mu.y) * rs.y + bt.y, 0.f);
    o.z = xv.z + fmaxf(gm.z * ((u.z + a.z) - mu.z) * rs.z + bt.z, 0.f);
    o.w = xv.w + fmaxf(gm.w * ((u.w + a.w) - mu.w) * rs.w + bt.w, 0.f);
    *(float4*)(out_x + base) = o;
}

// ---------------- launch -----------------------------------------------------------------
extern "C" void kernel_launch(void* const* d_in, const int* in_sizes, int n_in,
                              void* d_out, int out_size) {
    (void)in_sizes; (void)n_in; (void)out_size;
    const float* x  = (const float*)d_in[0];
    const void*  ei = d_in[1];
    const float* ea = (const float*)d_in[2];
    const float* Wu = (const float*)d_in[3];
    const float* bu = (const float*)d_in[4];
    const float* Wv = (const float*)d_in[5];
    const float* bv = (const float*)d_in[6];
    const float* WA = (const float*)d_in[7];
    const float* bA = (const float*)d_in[8];
    const float* WB = (const float*)d_in[9];
    const float* bB = (const float*)d_in[10];
    const float* WC = (const float*)d_in[11];
    const float* bC = (const float*)d_in[12];
    const float* gn_g = (const float*)d_in[13];
    const float* gn_b = (const float*)d_in[14];
    const float* ge_g = (const float*)d_in[15];
    const float* ge_b = (const float*)d_in[16];

    float* out   = (float*)d_out;
    float* out_x = out;
    float* out_e = out + (size_t)Nn * Dd;

    cudaFuncSetAttribute(node_mma_kernel, cudaFuncAttributeMaxDynamicSharedMemorySize, S_SIZE_N);
    cudaFuncSetAttribute(edge1_kernel, cudaFuncAttributeMaxDynamicSharedMemorySize, S_SIZE_E);

    detect_kernel<<<1, 256>>>((const unsigned*)ei);
    zero_kernel<<<2048, 256>>>();
    prep_w_kernel<<<5, 256>>>(Wu, Wv, WB, WC, WA);
    node_mma_kernel<<<dim3(74, 4), 256, S_SIZE_N>>>(x, bu, bv, bB, bC);
    edge1_kernel<<<296, 256, S_SIZE_E>>>(ea, ei, bA);
    finalize_kernel<<<1, 128>>>(0, 1.0f / (float)Ee);
    edge_pass2_kernel<<<(Ee + 7) / 8, 256>>>(ea, ei, ge_g, ge_b, out_e);
    node_stats_kernel<<<(Nn + 63) / 64, 128>>>();
    finalize_kernel<<<1, 128>>>(1, 1.0f / (float)Nn);
    node_out_kernel<<<(Nn * 32 + 255) / 256, 256>>>(x, gn_g, gn_b, out_x);
}